// round 1
// baseline (speedup 1.0000x reference)
#include <cuda_runtime.h>
#include <cuda_bf16.h>
#include <math.h>

// Problem constants (fixed by the dataset)
constexpr int cV = 50000;   // vocab
constexpr int cD = 256;     // embedding dim
constexpr int cH = 256;     // GRU hidden
constexpr int cB = 16;      // batch
constexpr int cT = 8;       // num_subtrees (time steps)
constexpr int cL = 512;     // subtree_len (nodes per graph)
constexpr int cE = 2048;    // edges per graph
constexpr int cG = cB * cT; // graphs = 128

// ------------------------- device scratch -------------------------
__device__ float g_embL[(size_t)cV * cD];   // emb_table @ Wl + bl
__device__ float g_embR[(size_t)cV * cD];   // emb_table @ Wr + br
__device__ int   g_tok[cG * cL];
__device__ float g_w[cG * cE];
__device__ float g_beta[cG];
__device__ float g_score[cG * cE];
__device__ float g_alpha[cG * cE];
__device__ float g_pooled[cG * cD];
__device__ float g_gi[2][cT * cB * 3 * cH];
__device__ float g_h[2][2][cB * cH];        // [dir][parity][b*H]
__device__ float g_ys[2][cT * cB * cH];

// ------------------------- f32x2 helpers -------------------------
__device__ __forceinline__ unsigned long long pk2(float x) {
    unsigned long long r;
    asm("mov.b64 %0, {%1, %1};" : "=l"(r) : "f"(x));
    return r;
}
__device__ __forceinline__ void fma2(unsigned long long& d, unsigned long long a,
                                     unsigned long long b) {
    asm("fma.rn.f32x2 %0, %1, %2, %0;" : "+l"(d) : "l"(a), "l"(b));
}
__device__ __forceinline__ float2 unpk(unsigned long long v) {
    float2 f;
    asm("mov.b64 {%0, %1}, %2;" : "=f"(f.x), "=f"(f.y) : "l"(v));
    return f;
}

// ------------------------- small utils -------------------------
__device__ __forceinline__ float warp_sum(float v) {
    #pragma unroll
    for (int o = 16; o > 0; o >>= 1) v += __shfl_xor_sync(0xffffffffu, v, o);
    return v;
}
__device__ __forceinline__ void atomicMaxF(float* addr, float val) {
    int* ia = (int*)addr;
    int old = __float_as_int(*addr);
    while (__int_as_float(old) < val) {
        int prev = atomicCAS(ia, old, __float_as_int(val));
        if (prev == old) break;
        old = prev;
    }
}
__device__ __forceinline__ float sigmoidf_(float x) { return 1.0f / (1.0f + expf(-x)); }

// ------------------------- K0: token LUT -------------------------
// g_tok[g][l] = token_ids[(t*L + l)*B + b], g = b*T + t
__global__ void k_tok(const int* __restrict__ token_ids) {
    int g = blockIdx.x, l = threadIdx.x;
    int b = g / cT, t = g % cT;
    g_tok[g * cL + l] = token_ids[(t * cL + l) * cB + b];
}

// zero the GRU h buffers
__global__ void k_zero() {
    int idx = blockIdx.x * 256 + threadIdx.x;  // 64 blocks * 256 = 16384
    ((float*)g_h)[idx] = 0.0f;
}

// ------------------------- K1: GEMM embL/embR -------------------------
// out = emb_table @ W + bias. M=50000, N=256, K=256. BM=128, BN=64, BK=16.
// 256 threads, per-thread 8x4 micro-tile via fma.rn.f32x2 (pairs along m).
__global__ void __launch_bounds__(256) k_gemm(const float* __restrict__ A,
                                              const float* __restrict__ Wl,
                                              const float* __restrict__ bl,
                                              const float* __restrict__ Wr,
                                              const float* __restrict__ br) {
    const int z  = blockIdx.z;
    const float* __restrict__ W    = z ? Wr : Wl;
    const float* __restrict__ bias = z ? br : bl;
    float* __restrict__ out        = z ? g_embR : g_embL;

    const int bm = blockIdx.x, bn = blockIdx.y;
    const int tid = threadIdx.x;
    const int tm = tid >> 4;   // 0..15 (m sub-tile of 8 rows)
    const int tn = tid & 15;   // 0..15 (n sub-tile of 4 cols)

    __shared__ float As[16][130];  // [k][m], stride 130 (8B-aligned rows, conflict-free)
    __shared__ float Bs[16][64];   // [k][n]

    unsigned long long acc[4][4];
    #pragma unroll
    for (int p = 0; p < 4; p++)
        #pragma unroll
        for (int n = 0; n < 4; n++) acc[p][n] = 0ull;

    for (int kb = 0; kb < 16; kb++) {
        // load A tile (128x16) transposed into As[k][m]
        #pragma unroll
        for (int i = 0; i < 2; i++) {
            int idx = tid + i * 256;
            int r = idx >> 2, c4 = idx & 3;
            int row = bm * 128 + r;
            if (row > cV - 1) row = cV - 1;
            float4 v = *(const float4*)(A + (size_t)row * cD + kb * 16 + c4 * 4);
            As[c4 * 4 + 0][r] = v.x;
            As[c4 * 4 + 1][r] = v.y;
            As[c4 * 4 + 2][r] = v.z;
            As[c4 * 4 + 3][r] = v.w;
        }
        // load B tile (16x64)
        {
            int c = tid >> 4, n4 = tid & 15;
            float4 v = *(const float4*)(W + (size_t)(kb * 16 + c) * cD + bn * 64 + n4 * 4);
            *(float4*)&Bs[c][n4 * 4] = v;
        }
        __syncthreads();

        #pragma unroll
        for (int k = 0; k < 16; k++) {
            const unsigned long long* ap =
                (const unsigned long long*)(&As[k][tm * 8]);
            unsigned long long a0 = ap[0], a1 = ap[1], a2 = ap[2], a3 = ap[3];
            float4 bv = *(const float4*)&Bs[k][tn * 4];
            unsigned long long b0 = pk2(bv.x), b1 = pk2(bv.y), b2 = pk2(bv.z),
                               b3 = pk2(bv.w);
            fma2(acc[0][0], a0, b0); fma2(acc[0][1], a0, b1);
            fma2(acc[0][2], a0, b2); fma2(acc[0][3], a0, b3);
            fma2(acc[1][0], a1, b0); fma2(acc[1][1], a1, b1);
            fma2(acc[1][2], a1, b2); fma2(acc[1][3], a1, b3);
            fma2(acc[2][0], a2, b0); fma2(acc[2][1], a2, b1);
            fma2(acc[2][2], a2, b2); fma2(acc[2][3], a2, b3);
            fma2(acc[3][0], a3, b0); fma2(acc[3][1], a3, b1);
            fma2(acc[3][2], a3, b2); fma2(acc[3][3], a3, b3);
        }
        __syncthreads();
    }

    const int col = bn * 64 + tn * 4;
    float4 bb = *(const float4*)(bias + col);
    #pragma unroll
    for (int p = 0; p < 4; p++) {
        float2 c0 = unpk(acc[p][0]), c1 = unpk(acc[p][1]);
        float2 c2 = unpk(acc[p][2]), c3 = unpk(acc[p][3]);
        int m0 = bm * 128 + tm * 8 + 2 * p;
        if (m0 < cV) {
            float4 o = make_float4(c0.x + bb.x, c1.x + bb.y, c2.x + bb.z, c3.x + bb.w);
            *(float4*)(out + (size_t)m0 * cD + col) = o;
        }
        if (m0 + 1 < cV) {
            float4 o = make_float4(c0.y + bb.x, c1.y + bb.y, c2.y + bb.z, c3.y + bb.w);
            *(float4*)(out + (size_t)(m0 + 1) * cD + col) = o;
        }
    }
}

// ------------------------- K2: edge pass 1 (w) -------------------------
// One warp per edge. w = sqrt(||emb[src]-emb[dst]||^2 + 1e-12)
__global__ void __launch_bounds__(256) k_w(const int* __restrict__ eidx,
                                           const float* __restrict__ emb) {
    int gw = blockIdx.x * 8 + (threadIdx.x >> 5);
    int lane = threadIdx.x & 31;
    int g = gw / cE, e = gw % cE;
    int src = eidx[(g * 2) * cE + e];
    int dst = eidx[(g * 2 + 1) * cE + e];
    int ts = g_tok[g * cL + src];
    int td = g_tok[g * cL + dst];
    const float4* ra = (const float4*)(emb + (size_t)ts * cD);
    const float4* rb = (const float4*)(emb + (size_t)td * cD);
    float ss = 0.0f;
    #pragma unroll
    for (int i = 0; i < 2; i++) {
        int j = lane + i * 32;
        float4 a = ra[j], b = rb[j];
        float dx = a.x - b.x, dy = a.y - b.y, dz = a.z - b.z, dw = a.w - b.w;
        ss += dx * dx + dy * dy + dz * dz + dw * dw;
    }
    ss = warp_sum(ss);
    if (lane == 0) g_w[gw] = sqrtf(ss + 1e-12f);
}

// ------------------------- K3: beta (mean w per graph) -------------------------
__global__ void __launch_bounds__(256) k_beta() {
    int g = blockIdx.x, tid = threadIdx.x;
    __shared__ float sm[256];
    float s = 0.0f;
    for (int e = tid; e < cE; e += 256) s += g_w[g * cE + e];
    sm[tid] = s;
    __syncthreads();
    for (int o = 128; o > 0; o >>= 1) {
        if (tid < o) sm[tid] += sm[tid + o];
        __syncthreads();
    }
    if (tid == 0) g_beta[g] = sm[0] / (float)cE;
}

// ------------------------- K4: edge pass 2 (score) -------------------------
__global__ void __launch_bounds__(256) k_score(const int* __restrict__ eidx,
                                               const float* __restrict__ We,
                                               const float* __restrict__ att) {
    int gw = blockIdx.x * 8 + (threadIdx.x >> 5);
    int lane = threadIdx.x & 31;
    int g = gw / cE, e = gw % cE;
    int src = eidx[(g * 2) * cE + e];
    int dst = eidx[(g * 2 + 1) * cE + e];
    int ts = g_tok[g * cL + src];
    int td = g_tok[g * cL + dst];
    float w = g_w[gw];
    float bt = g_beta[g];
    float ew = expf(-(w * w) / (2.0f * bt * bt));
    const float4* rl = (const float4*)(g_embL + (size_t)ts * cD);
    const float4* rr = (const float4*)(g_embR + (size_t)td * cD);
    const float4* rw = (const float4*)We;
    const float4* ra = (const float4*)att;
    float s = 0.0f;
    #pragma unroll
    for (int i = 0; i < 2; i++) {
        int j = lane + i * 32;
        float4 a = rl[j], b = rr[j], c = rw[j], at = ra[j];
        float vx = a.x + b.x + ew * c.x;
        float vy = a.y + b.y + ew * c.y;
        float vz = a.z + b.z + ew * c.z;
        float vw = a.w + b.w + ew * c.w;
        vx = vx > 0.0f ? vx : 0.2f * vx;
        vy = vy > 0.0f ? vy : 0.2f * vy;
        vz = vz > 0.0f ? vz : 0.2f * vz;
        vw = vw > 0.0f ? vw : 0.2f * vw;
        s += vx * at.x + vy * at.y + vz * at.z + vw * at.w;
    }
    s = warp_sum(s);
    if (lane == 0) g_score[gw] = s;
}

// ------------------------- K5: segment softmax -------------------------
__global__ void __launch_bounds__(512) k_soft(const int* __restrict__ eidx) {
    int g = blockIdx.x, tid = threadIdx.x;
    __shared__ float m[cL];
    __shared__ float den[cL];
    m[tid] = -1e30f;
    den[tid] = 0.0f;
    __syncthreads();
    for (int e = tid; e < cE; e += 512) {
        int d = eidx[(g * 2 + 1) * cE + e];
        atomicMaxF(&m[d], g_score[g * cE + e]);
    }
    __syncthreads();
    for (int e = tid; e < cE; e += 512) {
        int d = eidx[(g * 2 + 1) * cE + e];
        float ex = expf(g_score[g * cE + e] - m[d]);
        g_alpha[g * cE + e] = ex;
        atomicAdd(&den[d], ex);
    }
    __syncthreads();
    for (int e = tid; e < cE; e += 512) {
        int d = eidx[(g * 2 + 1) * cE + e];
        g_alpha[g * cE + e] = g_alpha[g * cE + e] / (den[d] + 1e-16f);
    }
}

// ------------------------- K6: aggregate + max-pool -------------------------
// One block (256 threads = D) per graph. Build CSR by dst in shared, then
// stream edges in chunks of 16 for MLP, per-thread accumulator per node,
// fold into the per-d max (including empty nodes = gat_bias only).
__global__ void __launch_bounds__(256) k_agg(const int* __restrict__ eidx,
                                             const float* __restrict__ gat_bias) {
    int g = blockIdx.x, tid = threadIdx.x;
    __shared__ int cnt[cL];
    __shared__ int off[cL + 1];
    __shared__ int srow[cE];
    __shared__ float salpha[cE];

    for (int l = tid; l < cL; l += 256) cnt[l] = 0;
    __syncthreads();
    for (int e = tid; e < cE; e += 256) {
        int d = eidx[(g * 2 + 1) * cE + e];
        atomicAdd(&cnt[d], 1);
    }
    __syncthreads();
    if (tid == 0) {
        int run = 0;
        for (int l = 0; l < cL; l++) {
            off[l] = run;
            run += cnt[l];
            cnt[l] = 0;
        }
        off[cL] = run;  // == cE
    }
    __syncthreads();
    for (int e = tid; e < cE; e += 256) {
        int d = eidx[(g * 2 + 1) * cE + e];
        int s = eidx[(g * 2) * cE + e];
        float a = g_alpha[g * cE + e];
        int tok = g_tok[g * cL + s];
        int pos = off[d] + atomicAdd(&cnt[d], 1);
        srow[pos] = tok;
        salpha[pos] = a;
    }
    __syncthreads();

    const int d = tid;
    const float bias = gat_bias[d];
    float pool = -1e30f;
    float acc = 0.0f;
    int cur = 0;
    int nxt = off[1];
    for (int base = 0; base < cE; base += 16) {
        float xv[16];
        #pragma unroll
        for (int j = 0; j < 16; j++)
            xv[j] = g_embL[(size_t)srow[base + j] * cD + d];
        #pragma unroll
        for (int j = 0; j < 16; j++) {
            int idx = base + j;
            while (idx >= nxt) {
                pool = fmaxf(pool, acc + bias);
                acc = 0.0f;
                cur++;
                nxt = off[cur + 1];
            }
            acc += salpha[idx] * xv[j];
        }
    }
    while (cur < cL) {
        pool = fmaxf(pool, acc + bias);
        acc = 0.0f;
        cur++;
    }
    g_pooled[g * cD + d] = pool;
}

// ------------------------- K7: GRU input gates (batched) -------------------------
// gi[dir][t*B+b][j] = pooled[b*T+t] @ Wih[dir].T + bih[dir]
__global__ void __launch_bounds__(256) k_gi(const float* __restrict__ Wihf,
                                            const float* __restrict__ bihf,
                                            const float* __restrict__ Wihb,
                                            const float* __restrict__ bihb) {
    int r = blockIdx.x;  // t*B + b
    int dir = blockIdx.y;
    int tid = threadIdx.x;
    int t = r / cB, b = r % cB;
    int g = b * cT + t;
    const float* __restrict__ Wih = dir ? Wihb : Wihf;
    const float* __restrict__ bih = dir ? bihb : bihf;
    __shared__ float x[cD];
    x[tid] = g_pooled[g * cD + tid];
    __syncthreads();
    const float4* xv = (const float4*)x;
    #pragma unroll
    for (int q = 0; q < 3; q++) {
        int j = q * 256 + tid;
        float s = bih[j];
        const float4* wr = (const float4*)(Wih + (size_t)j * cD);
        #pragma unroll 8
        for (int k4 = 0; k4 < 64; k4++) {
            float4 wv = wr[k4];
            float4 xx = xv[k4];
            s += wv.x * xx.x + wv.y * xx.y + wv.z * xx.z + wv.w * xx.w;
        }
        g_gi[dir][(size_t)r * 768 + j] = s;
    }
}

// ------------------------- K8: GRU step (one launch per step) -------------------------
// grid (16 chunks, 2 dirs), 256 threads: tid = jt*16 + b; thread owns
// output unit i = chunk*16 + jt for batch b; computes rows i, i+256, i+512 of gh.
__global__ void __launch_bounds__(256) k_step(int step,
                                              const float* __restrict__ Whhf,
                                              const float* __restrict__ bhhf,
                                              const float* __restrict__ Whhb,
                                              const float* __restrict__ bhhb) {
    const int dir = blockIdx.y;
    const int t = (dir == 0) ? step : (cT - 1 - step);
    const int pin = step & 1, pout = (step + 1) & 1;
    const int tid = threadIdx.x;
    const int b = tid & 15;
    const int jt = tid >> 4;
    const int i = blockIdx.x * 16 + jt;

    const float* __restrict__ Whh = dir ? Whhb : Whhf;
    const float* __restrict__ bhh = dir ? bhhb : bhhf;

    __shared__ float h[cB * cH];  // 16KB
    for (int idx = tid; idx < cB * cH; idx += 256) h[idx] = g_h[dir][pin][idx];
    __syncthreads();

    const float4* hv = (const float4*)(h + b * cH);
    const float4* w0 = (const float4*)(Whh + (size_t)i * cD);
    const float4* w1 = (const float4*)(Whh + (size_t)(i + 256) * cD);
    const float4* w2 = (const float4*)(Whh + (size_t)(i + 512) * cD);
    float hr = 0.0f, hz = 0.0f, hn = 0.0f;
    #pragma unroll 4
    for (int k4 = 0; k4 < 64; k4++) {
        float4 hh = hv[k4];
        float4 a = w0[k4], c = w1[k4], d = w2[k4];
        hr += a.x * hh.x + a.y * hh.y + a.z * hh.z + a.w * hh.w;
        hz += c.x * hh.x + c.y * hh.y + c.z * hh.z + c.w * hh.w;
        hn += d.x * hh.x + d.y * hh.y + d.z * hh.z + d.w * hh.w;
    }
    hr += bhh[i];
    hz += bhh[i + 256];
    hn += bhh[i + 512];

    const float* gi = &g_gi[dir][(size_t)(t * cB + b) * 768];
    float r = sigmoidf_(gi[i] + hr);
    float z = sigmoidf_(gi[i + 256] + hz);
    float n = tanhf(gi[i + 512] + r * hn);
    float hp = h[b * cH + i];
    float hnew = (1.0f - z) * n + z * hp;

    g_ys[dir][(size_t)(t * cB + b) * cH + i] = hnew;
    g_h[dir][pout][b * cH + i] = hnew;
}

// ------------------------- K9: finalize output -------------------------
// out[0:T*B*H) = ys_f + ys_b ; out[T*B*H : +B*H) = h_f ; then h_b
__global__ void __launch_bounds__(256) k_fin(float* __restrict__ out) {
    int idx = blockIdx.x * 256 + threadIdx.x;  // 160 blocks * 256 = 40960
    const int n1 = cT * cB * cH;               // 32768
    const int n2 = n1 + cB * cH;               // 36864
    if (idx < n1) {
        out[idx] = g_ys[0][idx] + g_ys[1][idx];
    } else if (idx < n2) {
        out[idx] = g_ys[0][(cT - 1) * cB * cH + (idx - n1)];
    } else {
        out[idx] = g_ys[1][idx - n2];
    }
}

// ------------------------- launch -------------------------
extern "C" void kernel_launch(void* const* d_in, const int* in_sizes, int n_in,
                              void* d_out, int out_size) {
    const int*   token_ids = (const int*)d_in[0];
    const int*   edge_index = (const int*)d_in[1];
    const float* emb  = (const float*)d_in[2];
    const float* Wl   = (const float*)d_in[3];
    const float* bl   = (const float*)d_in[4];
    const float* Wr   = (const float*)d_in[5];
    const float* br   = (const float*)d_in[6];
    const float* We   = (const float*)d_in[7];
    const float* att  = (const float*)d_in[8];
    const float* gbias = (const float*)d_in[9];
    const float* Wihf = (const float*)d_in[10];
    const float* Whhf = (const float*)d_in[11];
    const float* bihf = (const float*)d_in[12];
    const float* bhhf = (const float*)d_in[13];
    const float* Wihb = (const float*)d_in[14];
    const float* Whhb = (const float*)d_in[15];
    const float* bihb = (const float*)d_in[16];
    const float* bhhb = (const float*)d_in[17];
    float* out = (float*)d_out;

    k_tok<<<cG, cL>>>(token_ids);
    k_zero<<<64, 256>>>();
    k_gemm<<<dim3((cV + 127) / 128, cD / 64, 2), 256>>>(emb, Wl, bl, Wr, br);
    k_w<<<cG * cE / 8, 256>>>(edge_index, emb);
    k_beta<<<cG, 256>>>();
    k_score<<<cG * cE / 8, 256>>>(edge_index, We, att);
    k_soft<<<cG, 512>>>(edge_index);
    k_agg<<<cG, 256>>>(edge_index, gbias);
    k_gi<<<dim3(cT * cB, 2), 256>>>(Wihf, bihf, Wihb, bihb);
    for (int step = 0; step < cT; step++)
        k_step<<<dim3(16, 2), 256>>>(step, Whhf, bhhf, Whhb, bhhb);
    k_fin<<<160, 256>>>(out);
}

// round 4
// speedup vs baseline: 1.2755x; 1.2755x over previous
#include <cuda_runtime.h>
#include <cuda_bf16.h>
#include <cstdint>
#include <math.h>

// Problem constants (fixed by the dataset)
constexpr int cV = 50000;   // vocab
constexpr int cVp = 50048;  // vocab padded to 391*128
constexpr int cD = 256;     // embedding dim
constexpr int cH = 256;     // GRU hidden
constexpr int cB = 16;      // batch
constexpr int cT = 8;       // num_subtrees (time steps)
constexpr int cL = 512;     // subtree_len (nodes per graph)
constexpr int cE = 2048;    // edges per graph
constexpr int cG = cB * cT; // graphs = 128

// ------------------------- device scratch -------------------------
__device__ float g_embL[(size_t)cV * cD];   // emb_table @ Wl + bl
__device__ float g_embR[(size_t)cV * cD];   // emb_table @ Wr + br
__device__ __nv_bfloat16 g_Ahi[(size_t)cVp * cD];
__device__ __nv_bfloat16 g_Alo[(size_t)cVp * cD];
__device__ __nv_bfloat16 g_Bhi[2][cD * cD];  // W^T split hi: [z][n][k]
__device__ __nv_bfloat16 g_Blo[2][cD * cD];
__device__ int   g_tok[cG * cL];
__device__ float g_w[cG * cE];
__device__ float g_beta[cG];
__device__ float g_score[cG * cE];
__device__ float g_alpha[cG * cE];
__device__ float g_pooled[cG * cD];
__device__ float g_gi[2][cT * cB * 3 * cH];
__device__ float g_h[2][2][cB * cH];        // [dir][parity][b*H]
__device__ float g_ys[2][cT * cB * cH];

// ------------------------- small utils -------------------------
__device__ __forceinline__ float warp_sum(float v) {
    #pragma unroll
    for (int o = 16; o > 0; o >>= 1) v += __shfl_xor_sync(0xffffffffu, v, o);
    return v;
}
__device__ __forceinline__ void atomicMaxF(float* addr, float val) {
    int* ia = (int*)addr;
    int old = __float_as_int(*addr);
    while (__int_as_float(old) < val) {
        int prev = atomicCAS(ia, old, __float_as_int(val));
        if (prev == old) break;
        old = prev;
    }
}
__device__ __forceinline__ float sigmoidf_(float x) { return 1.0f / (1.0f + expf(-x)); }

// ------------------------- mma.sync helpers -------------------------
__device__ __forceinline__ uint32_t smem_u32(const void* p) {
    uint32_t a;
    asm("{ .reg .u64 t; cvta.to.shared.u64 t, %1; cvt.u32.u64 %0, t; }"
        : "=r"(a) : "l"(p));
    return a;
}
__device__ __forceinline__ void ldm_x4(uint32_t& r0, uint32_t& r1, uint32_t& r2,
                                       uint32_t& r3, uint32_t addr) {
    asm volatile("ldmatrix.sync.aligned.m8n8.x4.shared.b16 {%0,%1,%2,%3}, [%4];"
                 : "=r"(r0), "=r"(r1), "=r"(r2), "=r"(r3) : "r"(addr));
}
__device__ __forceinline__ void ldm_x2(uint32_t& r0, uint32_t& r1, uint32_t addr) {
    asm volatile("ldmatrix.sync.aligned.m8n8.x2.shared.b16 {%0,%1}, [%2];"
                 : "=r"(r0), "=r"(r1) : "r"(addr));
}
__device__ __forceinline__ void mma16816(float* d, uint32_t a0, uint32_t a1,
                                         uint32_t a2, uint32_t a3,
                                         uint32_t b0, uint32_t b1) {
    asm volatile(
        "mma.sync.aligned.m16n8k16.row.col.f32.bf16.bf16.f32 "
        "{%0,%1,%2,%3}, {%4,%5,%6,%7}, {%8,%9}, {%0,%1,%2,%3};"
        : "+f"(d[0]), "+f"(d[1]), "+f"(d[2]), "+f"(d[3])
        : "r"(a0), "r"(a1), "r"(a2), "r"(a3), "r"(b0), "r"(b1));
}

// ------------------------- K0: token LUT -------------------------
__global__ void k_tok(const int* __restrict__ token_ids) {
    int g = blockIdx.x, l = threadIdx.x;
    int b = g / cT, t = g % cT;
    g_tok[g * cL + l] = token_ids[(t * cL + l) * cB + b];
}

__global__ void k_zero() {
    int idx = blockIdx.x * 256 + threadIdx.x;
    ((float*)g_h)[idx] = 0.0f;
}

// ------------------------- split-precision conversion -------------------------
__global__ void __launch_bounds__(256) k_splitA(const float* __restrict__ emb) {
    size_t idx = ((size_t)blockIdx.x * 256 + threadIdx.x) * 8;
    int row = (int)(idx >> 8);
    float v[8];
    if (row < cV) {
        float4 a = *(const float4*)(emb + idx);
        float4 b = *(const float4*)(emb + idx + 4);
        v[0] = a.x; v[1] = a.y; v[2] = a.z; v[3] = a.w;
        v[4] = b.x; v[5] = b.y; v[6] = b.z; v[7] = b.w;
    } else {
        #pragma unroll
        for (int i = 0; i < 8; i++) v[i] = 0.0f;
    }
    __nv_bfloat16 hi[8], lo[8];
    #pragma unroll
    for (int i = 0; i < 8; i++) {
        hi[i] = __float2bfloat16_rn(v[i]);
        lo[i] = __float2bfloat16_rn(v[i] - __bfloat162float(hi[i]));
    }
    *(uint4*)(g_Ahi + idx) = *(uint4*)hi;
    *(uint4*)(g_Alo + idx) = *(uint4*)lo;
}

// W -> W^T hi/lo bf16 (B operand is [n][k], K-contiguous)
__global__ void __launch_bounds__(256) k_splitB(const float* __restrict__ Wl,
                                                const float* __restrict__ Wr) {
    int z = blockIdx.y, n = blockIdx.x, k = threadIdx.x;
    const float* W = z ? Wr : Wl;
    float x = W[(size_t)k * cD + n];
    __nv_bfloat16 hi = __float2bfloat16_rn(x);
    __nv_bfloat16 lo = __float2bfloat16_rn(x - __bfloat162float(hi));
    g_Bhi[z][n * cD + k] = hi;
    g_Blo[z][n * cD + k] = lo;
}

// ------------------------- K1: mma.sync bf16 split GEMM -------------------------
// out[m,n] = sum_k A[m,k] W[k,n] + bias[n]
// 3 bf16 passes (AhiBhi + AhiBlo + AloBhi), fp32 accum.
// Grid (391 m-tiles, 2 n-tiles, 2 z). CTA 256 thr (8 warps), tile 128x128.
// Warp grid 2(m) x 4(n), warp tile 64x32; K chunked 4x64 in smem.
constexpr int SSTRIDE = 72;                       // halves per smem row (144B)
constexpr int TILE_HALV = 128 * SSTRIDE;          // 9216 halves = 18432 B
constexpr int SMEM_GEMM = 4 * TILE_HALV * 2;      // 73728 B

__global__ void __launch_bounds__(256, 1)
k_gemm_mma(const float* __restrict__ bl, const float* __restrict__ br) {
    extern __shared__ __nv_bfloat16 sm[];
    __nv_bfloat16* As_h = sm;
    __nv_bfloat16* As_l = sm + TILE_HALV;
    __nv_bfloat16* Bs_h = sm + 2 * TILE_HALV;
    __nv_bfloat16* Bs_l = sm + 3 * TILE_HALV;

    const int tid = threadIdx.x, wid = tid >> 5, lane = tid & 31;
    const int m0 = blockIdx.x * 128;
    const int n0 = blockIdx.y * 128;
    const int z = blockIdx.z;
    const __nv_bfloat16* __restrict__ gBh = g_Bhi[z];
    const __nv_bfloat16* __restrict__ gBl = g_Blo[z];
    const float* __restrict__ bias = z ? br : bl;
    float* __restrict__ out = z ? g_embR : g_embL;

    const int mw = (wid & 1) * 64;   // warp m offset in CTA tile
    const int nw = (wid >> 1) * 32;  // warp n offset

    const uint32_t uAh = smem_u32(As_h);
    const uint32_t uAl = smem_u32(As_l);
    const uint32_t uBh = smem_u32(Bs_h);
    const uint32_t uBl = smem_u32(Bs_l);

    float acc[4][4][4];
    #pragma unroll
    for (int mi = 0; mi < 4; mi++)
        #pragma unroll
        for (int ni = 0; ni < 4; ni++)
            #pragma unroll
            for (int q = 0; q < 4; q++) acc[mi][ni][q] = 0.0f;

    // ldmatrix per-lane base offsets (in halves)
    const int aRow = mw + (lane & 15);
    const int aKof = (lane >> 4) * 8;
    const int bRow = nw + (lane & 7);
    const int bKof = ((lane >> 3) & 1) * 8;

    for (int kb = 0; kb < 256; kb += 64) {
        // stage A (128 rows x 64 halves) hi+lo
        #pragma unroll
        for (int i = 0; i < 4; i++) {
            int idx = tid + i * 256;
            int r = idx >> 3, s = idx & 7;
            size_t gsrc = (size_t)(m0 + r) * cD + kb + s * 8;
            int dst = r * SSTRIDE + s * 8;
            *(uint4*)(As_h + dst) = *(const uint4*)(g_Ahi + gsrc);
            *(uint4*)(As_l + dst) = *(const uint4*)(g_Alo + gsrc);
        }
        // stage B (128 n-rows x 64 halves) hi+lo
        #pragma unroll
        for (int i = 0; i < 4; i++) {
            int idx = tid + i * 256;
            int r = idx >> 3, s = idx & 7;
            size_t gsrc = (size_t)(n0 + r) * cD + kb + s * 8;
            int dst = r * SSTRIDE + s * 8;
            *(uint4*)(Bs_h + dst) = *(const uint4*)(gBh + gsrc);
            *(uint4*)(Bs_l + dst) = *(const uint4*)(gBl + gsrc);
        }
        __syncthreads();

        #pragma unroll
        for (int ks = 0; ks < 4; ks++) {
            const int kk = ks * 16;
            uint32_t ah[4][4], al[4][4], bh[4][2], bl2[4][2];
            #pragma unroll
            for (int mi = 0; mi < 4; mi++) {
                uint32_t off =
                    (uint32_t)(((aRow + mi * 16) * SSTRIDE + kk + aKof) * 2);
                ldm_x4(ah[mi][0], ah[mi][1], ah[mi][2], ah[mi][3], uAh + off);
                ldm_x4(al[mi][0], al[mi][1], al[mi][2], al[mi][3], uAl + off);
            }
            #pragma unroll
            for (int ni = 0; ni < 4; ni++) {
                uint32_t off =
                    (uint32_t)(((bRow + ni * 8) * SSTRIDE + kk + bKof) * 2);
                ldm_x2(bh[ni][0], bh[ni][1], uBh + off);
                ldm_x2(bl2[ni][0], bl2[ni][1], uBl + off);
            }
            #pragma unroll
            for (int mi = 0; mi < 4; mi++)
                #pragma unroll
                for (int ni = 0; ni < 4; ni++) {
                    mma16816(acc[mi][ni], ah[mi][0], ah[mi][1], ah[mi][2],
                             ah[mi][3], bh[ni][0], bh[ni][1]);
                    mma16816(acc[mi][ni], ah[mi][0], ah[mi][1], ah[mi][2],
                             ah[mi][3], bl2[ni][0], bl2[ni][1]);
                    mma16816(acc[mi][ni], al[mi][0], al[mi][1], al[mi][2],
                             al[mi][3], bh[ni][0], bh[ni][1]);
                }
        }
        __syncthreads();
    }

    // epilogue: D layout d0,d1 = (r, 2c),(r,2c+1); d2,d3 = (r+8, ...)
    float2 bias2[4];
    #pragma unroll
    for (int ni = 0; ni < 4; ni++)
        bias2[ni] = *(const float2*)(bias + n0 + nw + ni * 8 + (lane & 3) * 2);

    const int mbase = m0 + mw + (lane >> 2);
    #pragma unroll
    for (int mi = 0; mi < 4; mi++) {
        int mg0 = mbase + mi * 16;
        int mg1 = mg0 + 8;
        #pragma unroll
        for (int ni = 0; ni < 4; ni++) {
            int n = n0 + nw + ni * 8 + (lane & 3) * 2;
            if (mg0 < cV) {
                float2 o = make_float2(acc[mi][ni][0] + bias2[ni].x,
                                       acc[mi][ni][1] + bias2[ni].y);
                *(float2*)(out + (size_t)mg0 * cD + n) = o;
            }
            if (mg1 < cV) {
                float2 o = make_float2(acc[mi][ni][2] + bias2[ni].x,
                                       acc[mi][ni][3] + bias2[ni].y);
                *(float2*)(out + (size_t)mg1 * cD + n) = o;
            }
        }
    }
}

// ------------------------- K2: edge pass 1 (w) -------------------------
__global__ void __launch_bounds__(256) k_w(const int* __restrict__ eidx,
                                           const float* __restrict__ emb) {
    int gw = blockIdx.x * 8 + (threadIdx.x >> 5);
    int lane = threadIdx.x & 31;
    int g = gw / cE, e = gw % cE;
    int src = eidx[(g * 2) * cE + e];
    int dst = eidx[(g * 2 + 1) * cE + e];
    int ts = g_tok[g * cL + src];
    int td = g_tok[g * cL + dst];
    const float4* ra = (const float4*)(emb + (size_t)ts * cD);
    const float4* rb = (const float4*)(emb + (size_t)td * cD);
    float ss = 0.0f;
    #pragma unroll
    for (int i = 0; i < 2; i++) {
        int j = lane + i * 32;
        float4 a = ra[j], b = rb[j];
        float dx = a.x - b.x, dy = a.y - b.y, dz = a.z - b.z, dw = a.w - b.w;
        ss += dx * dx + dy * dy + dz * dz + dw * dw;
    }
    ss = warp_sum(ss);
    if (lane == 0) g_w[gw] = sqrtf(ss + 1e-12f);
}

// ------------------------- K3: beta -------------------------
__global__ void __launch_bounds__(256) k_beta() {
    int g = blockIdx.x, tid = threadIdx.x;
    __shared__ float sm[256];
    float s = 0.0f;
    for (int e = tid; e < cE; e += 256) s += g_w[g * cE + e];
    sm[tid] = s;
    __syncthreads();
    for (int o = 128; o > 0; o >>= 1) {
        if (tid < o) sm[tid] += sm[tid + o];
        __syncthreads();
    }
    if (tid == 0) g_beta[g] = sm[0] / (float)cE;
}

// ------------------------- K4: edge pass 2 (score) -------------------------
__global__ void __launch_bounds__(256) k_score(const int* __restrict__ eidx,
                                               const float* __restrict__ We,
                                               const float* __restrict__ att) {
    int gw = blockIdx.x * 8 + (threadIdx.x >> 5);
    int lane = threadIdx.x & 31;
    int g = gw / cE, e = gw % cE;
    int src = eidx[(g * 2) * cE + e];
    int dst = eidx[(g * 2 + 1) * cE + e];
    int ts = g_tok[g * cL + src];
    int td = g_tok[g * cL + dst];
    float w = g_w[gw];
    float bt = g_beta[g];
    float ew = expf(-(w * w) / (2.0f * bt * bt));
    const float4* rl = (const float4*)(g_embL + (size_t)ts * cD);
    const float4* rr = (const float4*)(g_embR + (size_t)td * cD);
    const float4* rw = (const float4*)We;
    const float4* ra = (const float4*)att;
    float s = 0.0f;
    #pragma unroll
    for (int i = 0; i < 2; i++) {
        int j = lane + i * 32;
        float4 a = rl[j], b = rr[j], c = rw[j], at = ra[j];
        float vx = a.x + b.x + ew * c.x;
        float vy = a.y + b.y + ew * c.y;
        float vz = a.z + b.z + ew * c.z;
        float vw = a.w + b.w + ew * c.w;
        vx = vx > 0.0f ? vx : 0.2f * vx;
        vy = vy > 0.0f ? vy : 0.2f * vy;
        vz = vz > 0.0f ? vz : 0.2f * vz;
        vw = vw > 0.0f ? vw : 0.2f * vw;
        s += vx * at.x + vy * at.y + vz * at.z + vw * at.w;
    }
    s = warp_sum(s);
    if (lane == 0) g_score[gw] = s;
}

// ------------------------- K5: segment softmax -------------------------
__global__ void __launch_bounds__(512) k_soft(const int* __restrict__ eidx) {
    int g = blockIdx.x, tid = threadIdx.x;
    __shared__ float m[cL];
    __shared__ float den[cL];
    m[tid] = -1e30f;
    den[tid] = 0.0f;
    __syncthreads();
    for (int e = tid; e < cE; e += 512) {
        int d = eidx[(g * 2 + 1) * cE + e];
        atomicMaxF(&m[d], g_score[g * cE + e]);
    }
    __syncthreads();
    for (int e = tid; e < cE; e += 512) {
        int d = eidx[(g * 2 + 1) * cE + e];
        float ex = expf(g_score[g * cE + e] - m[d]);
        g_alpha[g * cE + e] = ex;
        atomicAdd(&den[d], ex);
    }
    __syncthreads();
    for (int e = tid; e < cE; e += 512) {
        int d = eidx[(g * 2 + 1) * cE + e];
        g_alpha[g * cE + e] = g_alpha[g * cE + e] / (den[d] + 1e-16f);
    }
}

// ------------------------- K6: aggregate + max-pool -------------------------
__global__ void __launch_bounds__(256) k_agg(const int* __restrict__ eidx,
                                             const float* __restrict__ gat_bias) {
    int g = blockIdx.x, tid = threadIdx.x;
    __shared__ int cnt[cL];
    __shared__ int off[cL + 1];
    __shared__ int srow[cE];
    __shared__ float salpha[cE];

    for (int l = tid; l < cL; l += 256) cnt[l] = 0;
    __syncthreads();
    for (int e = tid; e < cE; e += 256) {
        int d = eidx[(g * 2 + 1) * cE + e];
        atomicAdd(&cnt[d], 1);
    }
    __syncthreads();
    if (tid == 0) {
        int run = 0;
        for (int l = 0; l < cL; l++) {
            off[l] = run;
            run += cnt[l];
            cnt[l] = 0;
        }
        off[cL] = run;
    }
    __syncthreads();
    for (int e = tid; e < cE; e += 256) {
        int d = eidx[(g * 2 + 1) * cE + e];
        int s = eidx[(g * 2) * cE + e];
        float a = g_alpha[g * cE + e];
        int tok = g_tok[g * cL + s];
        int pos = off[d] + atomicAdd(&cnt[d], 1);
        srow[pos] = tok;
        salpha[pos] = a;
    }
    __syncthreads();

    const int d = tid;
    const float bias = gat_bias[d];
    float pool = -1e30f;
    float acc = 0.0f;
    int cur = 0;
    int nxt = off[1];
    for (int base = 0; base < cE; base += 16) {
        float xv[16];
        #pragma unroll
        for (int j = 0; j < 16; j++)
            xv[j] = g_embL[(size_t)srow[base + j] * cD + d];
        #pragma unroll
        for (int j = 0; j < 16; j++) {
            int idx = base + j;
            while (idx >= nxt) {
                pool = fmaxf(pool, acc + bias);
                acc = 0.0f;
                cur++;
                nxt = off[cur + 1];
            }
            acc += salpha[idx] * xv[j];
        }
    }
    while (cur < cL) {
        pool = fmaxf(pool, acc + bias);
        acc = 0.0f;
        cur++;
    }
    g_pooled[g * cD + d] = pool;
}

// ------------------------- K7: GRU input gates -------------------------
__global__ void __launch_bounds__(256) k_gi(const float* __restrict__ Wihf,
                                            const float* __restrict__ bihf,
                                            const float* __restrict__ Wihb,
                                            const float* __restrict__ bihb) {
    int r = blockIdx.x;
    int dir = blockIdx.y;
    int tid = threadIdx.x;
    int t = r / cB, b = r % cB;
    int g = b * cT + t;
    const float* __restrict__ Wih = dir ? Wihb : Wihf;
    const float* __restrict__ bih = dir ? bihb : bihf;
    __shared__ float x[cD];
    x[tid] = g_pooled[g * cD + tid];
    __syncthreads();
    const float4* xv = (const float4*)x;
    #pragma unroll
    for (int q = 0; q < 3; q++) {
        int j = q * 256 + tid;
        float s = bih[j];
        const float4* wr = (const float4*)(Wih + (size_t)j * cD);
        #pragma unroll 8
        for (int k4 = 0; k4 < 64; k4++) {
            float4 wv = wr[k4];
            float4 xx = xv[k4];
            s += wv.x * xx.x + wv.y * xx.y + wv.z * xx.z + wv.w * xx.w;
        }
        g_gi[dir][(size_t)r * 768 + j] = s;
    }
}

// ------------------------- K8: GRU step -------------------------
__global__ void __launch_bounds__(256) k_step(int step,
                                              const float* __restrict__ Whhf,
                                              const float* __restrict__ bhhf,
                                              const float* __restrict__ Whhb,
                                              const float* __restrict__ bhhb) {
    const int dir = blockIdx.y;
    const int t = (dir == 0) ? step : (cT - 1 - step);
    const int pin = step & 1, pout = (step + 1) & 1;
    const int tid = threadIdx.x;
    const int b = tid & 15;
    const int jt = tid >> 4;
    const int i = blockIdx.x * 16 + jt;

    const float* __restrict__ Whh = dir ? Whhb : Whhf;
    const float* __restrict__ bhh = dir ? bhhb : bhhf;

    __shared__ float h[cB * cH];
    for (int idx = tid; idx < cB * cH; idx += 256) h[idx] = g_h[dir][pin][idx];
    __syncthreads();

    const float4* hv = (const float4*)(h + b * cH);
    const float4* w0 = (const float4*)(Whh + (size_t)i * cD);
    const float4* w1 = (const float4*)(Whh + (size_t)(i + 256) * cD);
    const float4* w2 = (const float4*)(Whh + (size_t)(i + 512) * cD);
    float hr = 0.0f, hz = 0.0f, hn = 0.0f;
    #pragma unroll 4
    for (int k4 = 0; k4 < 64; k4++) {
        float4 hh = hv[k4];
        float4 a = w0[k4], c = w1[k4], d = w2[k4];
        hr += a.x * hh.x + a.y * hh.y + a.z * hh.z + a.w * hh.w;
        hz += c.x * hh.x + c.y * hh.y + c.z * hh.z + c.w * hh.w;
        hn += d.x * hh.x + d.y * hh.y + d.z * hh.z + d.w * hh.w;
    }
    hr += bhh[i];
    hz += bhh[i + 256];
    hn += bhh[i + 512];

    const float* gi = &g_gi[dir][(size_t)(t * cB + b) * 768];
    float r = sigmoidf_(gi[i] + hr);
    float z = sigmoidf_(gi[i + 256] + hz);
    float n = tanhf(gi[i + 512] + r * hn);
    float hp = h[b * cH + i];
    float hnew = (1.0f - z) * n + z * hp;

    g_ys[dir][(size_t)(t * cB + b) * cH + i] = hnew;
    g_h[dir][pout][b * cH + i] = hnew;
}

// ------------------------- K9: finalize output -------------------------
__global__ void __launch_bounds__(256) k_fin(float* __restrict__ out) {
    int idx = blockIdx.x * 256 + threadIdx.x;
    const int n1 = cT * cB * cH;
    const int n2 = n1 + cB * cH;
    if (idx < n1) {
        out[idx] = g_ys[0][idx] + g_ys[1][idx];
    } else if (idx < n2) {
        out[idx] = g_ys[0][(cT - 1) * cB * cH + (idx - n1)];
    } else {
        out[idx] = g_ys[1][idx - n2];
    }
}

// ------------------------- launch -------------------------
extern "C" void kernel_launch(void* const* d_in, const int* in_sizes, int n_in,
                              void* d_out, int out_size) {
    const int*   token_ids = (const int*)d_in[0];
    const int*   edge_index = (const int*)d_in[1];
    const float* emb  = (const float*)d_in[2];
    const float* Wl   = (const float*)d_in[3];
    const float* bl   = (const float*)d_in[4];
    const float* Wr   = (const float*)d_in[5];
    const float* br   = (const float*)d_in[6];
    const float* We   = (const float*)d_in[7];
    const float* att  = (const float*)d_in[8];
    const float* gbias = (const float*)d_in[9];
    const float* Wihf = (const float*)d_in[10];
    const float* Whhf = (const float*)d_in[11];
    const float* bihf = (const float*)d_in[12];
    const float* bhhf = (const float*)d_in[13];
    const float* Wihb = (const float*)d_in[14];
    const float* Whhb = (const float*)d_in[15];
    const float* bihb = (const float*)d_in[16];
    const float* bhhb = (const float*)d_in[17];
    float* out = (float*)d_out;

    cudaFuncSetAttribute(k_gemm_mma,
                         cudaFuncAttributeMaxDynamicSharedMemorySize, SMEM_GEMM);

    k_tok<<<cG, cL>>>(token_ids);
    k_zero<<<64, 256>>>();
    k_splitA<<<(int)(((size_t)cVp * cD) / (256 * 8)), 256>>>(emb);
    k_splitB<<<dim3(cD, 2), cD>>>(Wl, Wr);
    k_gemm_mma<<<dim3(cVp / 128, 2, 2), 256, SMEM_GEMM>>>(bl, br);
    k_w<<<cG * cE / 8, 256>>>(edge_index, emb);
    k_beta<<<cG, 256>>>();
    k_score<<<cG * cE / 8, 256>>>(edge_index, We, att);
    k_soft<<<cG, 512>>>(edge_index);
    k_agg<<<cG, 256>>>(edge_index, gbias);
    k_gi<<<dim3(cT * cB, 2), 256>>>(Wihf, bihf, Wihb, bihb);
    for (int step = 0; step < cT; step++)
        k_step<<<dim3(16, 2), 256>>>(step, Whhf, bhhf, Whhb, bhhb);
    k_fin<<<160, 256>>>(out);
}

// round 5
// speedup vs baseline: 1.2852x; 1.0076x over previous
#include <cuda_runtime.h>
#include <cuda_bf16.h>
#include <cstdint>
#include <math.h>

// Problem constants (fixed by the dataset)
constexpr int cV = 50000;   // vocab
constexpr int cVp = 50048;  // vocab padded to 391*128
constexpr int cD = 256;     // embedding dim
constexpr int cH = 256;     // GRU hidden
constexpr int cB = 16;      // batch
constexpr int cT = 8;       // num_subtrees (time steps)
constexpr int cL = 512;     // subtree_len (nodes per graph)
constexpr int cE = 2048;    // edges per graph
constexpr int cG = cB * cT; // graphs = 128

// ------------------------- device scratch -------------------------
__device__ float g_embL[(size_t)cV * cD];   // emb_table @ Wl + bl
__device__ float g_embR[(size_t)cV * cD];   // emb_table @ Wr + br
__device__ __nv_bfloat16 g_Ahi[(size_t)cVp * cD];
__device__ __nv_bfloat16 g_Alo[(size_t)cVp * cD];
__device__ __nv_bfloat16 g_Bhi[2][cD * cD];  // W^T split hi: [z][n][k]
__device__ __nv_bfloat16 g_Blo[2][cD * cD];
__device__ int   g_tok[cG * cL];
__device__ float g_w[cG * cE];
__device__ float g_beta[cG];
__device__ float g_score[cG * cE];
__device__ float g_alpha[cG * cE];
__device__ float g_pooled[cG * cD];
__device__ float g_gi[2][cT * cB * 3 * cH];
__device__ float g_h[2][2][cB * cH];        // [dir][parity][b*H]
__device__ float g_ys[2][cT * cB * cH];

// ------------------------- small utils -------------------------
__device__ __forceinline__ float warp_sum(float v) {
    #pragma unroll
    for (int o = 16; o > 0; o >>= 1) v += __shfl_xor_sync(0xffffffffu, v, o);
    return v;
}
__device__ __forceinline__ void atomicMaxF(float* addr, float val) {
    int* ia = (int*)addr;
    int old = __float_as_int(*addr);
    while (__int_as_float(old) < val) {
        int prev = atomicCAS(ia, old, __float_as_int(val));
        if (prev == old) break;
        old = prev;
    }
}
__device__ __forceinline__ float sigmoidf_(float x) { return 1.0f / (1.0f + expf(-x)); }

// ------------------------- mma.sync helpers -------------------------
__device__ __forceinline__ uint32_t smem_u32(const void* p) {
    uint32_t a;
    asm("{ .reg .u64 t; cvta.to.shared.u64 t, %1; cvt.u32.u64 %0, t; }"
        : "=r"(a) : "l"(p));
    return a;
}
__device__ __forceinline__ void ldm_x4(uint32_t& r0, uint32_t& r1, uint32_t& r2,
                                       uint32_t& r3, uint32_t addr) {
    asm volatile("ldmatrix.sync.aligned.m8n8.x4.shared.b16 {%0,%1,%2,%3}, [%4];"
                 : "=r"(r0), "=r"(r1), "=r"(r2), "=r"(r3) : "r"(addr));
}
__device__ __forceinline__ void ldm_x2(uint32_t& r0, uint32_t& r1, uint32_t addr) {
    asm volatile("ldmatrix.sync.aligned.m8n8.x2.shared.b16 {%0,%1}, [%2];"
                 : "=r"(r0), "=r"(r1) : "r"(addr));
}
__device__ __forceinline__ void mma16816(float* d, uint32_t a0, uint32_t a1,
                                         uint32_t a2, uint32_t a3,
                                         uint32_t b0, uint32_t b1) {
    asm volatile(
        "mma.sync.aligned.m16n8k16.row.col.f32.bf16.bf16.f32 "
        "{%0,%1,%2,%3}, {%4,%5,%6,%7}, {%8,%9}, {%0,%1,%2,%3};"
        : "+f"(d[0]), "+f"(d[1]), "+f"(d[2]), "+f"(d[3])
        : "r"(a0), "r"(a1), "r"(a2), "r"(a3), "r"(b0), "r"(b1));
}
__device__ __forceinline__ void cpa16(uint32_t dst, const void* src) {
    asm volatile("cp.async.cg.shared.global [%0], [%1], 16;" :: "r"(dst),
                 "l"(src));
}
__device__ __forceinline__ void cpa_commit() {
    asm volatile("cp.async.commit_group;" ::: "memory");
}
__device__ __forceinline__ void cpa_wait0() {
    asm volatile("cp.async.wait_group 0;" ::: "memory");
}

// ------------------------- K0: token LUT -------------------------
__global__ void k_tok(const int* __restrict__ token_ids) {
    int g = blockIdx.x, l = threadIdx.x;
    int b = g / cT, t = g % cT;
    g_tok[g * cL + l] = token_ids[(t * cL + l) * cB + b];
}

__global__ void k_zero() {
    int idx = blockIdx.x * 256 + threadIdx.x;
    ((float*)g_h)[idx] = 0.0f;
}

// ------------------------- split-precision conversion -------------------------
__global__ void __launch_bounds__(256) k_splitA(const float* __restrict__ emb) {
    size_t idx = ((size_t)blockIdx.x * 256 + threadIdx.x) * 8;
    int row = (int)(idx >> 8);
    float v[8];
    if (row < cV) {
        float4 a = *(const float4*)(emb + idx);
        float4 b = *(const float4*)(emb + idx + 4);
        v[0] = a.x; v[1] = a.y; v[2] = a.z; v[3] = a.w;
        v[4] = b.x; v[5] = b.y; v[6] = b.z; v[7] = b.w;
    } else {
        #pragma unroll
        for (int i = 0; i < 8; i++) v[i] = 0.0f;
    }
    __nv_bfloat16 hi[8], lo[8];
    #pragma unroll
    for (int i = 0; i < 8; i++) {
        hi[i] = __float2bfloat16_rn(v[i]);
        lo[i] = __float2bfloat16_rn(v[i] - __bfloat162float(hi[i]));
    }
    *(uint4*)(g_Ahi + idx) = *(uint4*)hi;
    *(uint4*)(g_Alo + idx) = *(uint4*)lo;
}

// W -> W^T hi/lo bf16 (B operand is [n][k], K-contiguous)
__global__ void __launch_bounds__(256) k_splitB(const float* __restrict__ Wl,
                                                const float* __restrict__ Wr) {
    int z = blockIdx.y, n = blockIdx.x, k = threadIdx.x;
    const float* W = z ? Wr : Wl;
    float x = W[(size_t)k * cD + n];
    __nv_bfloat16 hi = __float2bfloat16_rn(x);
    __nv_bfloat16 lo = __float2bfloat16_rn(x - __bfloat162float(hi));
    g_Bhi[z][n * cD + k] = hi;
    g_Blo[z][n * cD + k] = lo;
}

// ------------------------- K1: mma.sync bf16 split GEMM (A-resident) ------
// out[m,n] = sum_k A[m,k] W[k,n] + bias[n]
// 3 bf16 passes (AhiBhi + AhiBlo + AloBhi), fp32 accum.
// Grid: 391 CTAs (one 128-row m-tile each). K=256 fully smem-resident.
// CTA loops over 2 z x 4 n-chunks(64); B chunk staged via cp.async.
// Warp grid 2m x 4n over 128x64; warp tile 64x16.
constexpr int KHS = 264;  // halves per smem row (528 B, pad 8)
constexpr int SM2_AH = 0;
constexpr int SM2_AL = 128 * KHS;
constexpr int SM2_BH = 2 * 128 * KHS;
constexpr int SM2_BL = 2 * 128 * KHS + 64 * KHS;
constexpr int SMEM2 = (2 * 128 * KHS + 2 * 64 * KHS) * 2;  // 202752 B

__global__ void __launch_bounds__(256, 1)
k_gemm2(const float* __restrict__ bl, const float* __restrict__ br) {
    extern __shared__ __nv_bfloat16 sm2[];
    const uint32_t sb = smem_u32(sm2);
    const int tid = threadIdx.x, wid = tid >> 5, lane = tid & 31;
    const int m0 = blockIdx.x * 128;

    // ---- stage A (hi+lo), 128 rows x 256 halves, cp.async ----
    #pragma unroll
    for (int i = 0; i < 16; i++) {
        int idx = tid + i * 256;
        int r = idx >> 5, c = idx & 31;
        size_t gs = (size_t)(m0 + r) * cD + c * 8;
        uint32_t d = (uint32_t)((r * KHS + c * 8) * 2);
        cpa16(sb + SM2_AH * 2 + d, g_Ahi + gs);
        cpa16(sb + SM2_AL * 2 + d, g_Alo + gs);
    }
    cpa_commit();

    const int mw = (wid & 1) * 64;
    const int nwp = (wid >> 1) * 16;
    const int aRow = mw + (lane & 15);
    const int aK = (lane >> 4) * 8;
    const int bRow = nwp + (lane & 7);
    const int bK = ((lane >> 3) & 1) * 8;

    #pragma unroll 1
    for (int iter = 0; iter < 8; iter++) {
        const int z = iter >> 2, nc = iter & 3;
        const __nv_bfloat16* __restrict__ gBh = g_Bhi[z];
        const __nv_bfloat16* __restrict__ gBl = g_Blo[z];

        // ---- stage B chunk (hi+lo), 64 n-rows x 256 halves ----
        #pragma unroll
        for (int i = 0; i < 8; i++) {
            int idx = tid + i * 256;
            int r = idx >> 5, c = idx & 31;
            size_t gs = (size_t)(nc * 64 + r) * cD + c * 8;
            uint32_t d = (uint32_t)((r * KHS + c * 8) * 2);
            cpa16(sb + SM2_BH * 2 + d, gBh + gs);
            cpa16(sb + SM2_BL * 2 + d, gBl + gs);
        }
        cpa_commit();
        cpa_wait0();
        __syncthreads();

        float acc[4][2][4];
        #pragma unroll
        for (int mi = 0; mi < 4; mi++)
            #pragma unroll
            for (int ni = 0; ni < 2; ni++)
                #pragma unroll
                for (int q = 0; q < 4; q++) acc[mi][ni][q] = 0.0f;

        #pragma unroll 4
        for (int ks = 0; ks < 16; ks++) {
            const int kk = ks * 16;
            uint32_t ah[4][4], al[4][4], bh[2][2], bl2[2][2];
            #pragma unroll
            for (int mi = 0; mi < 4; mi++) {
                uint32_t off =
                    (uint32_t)(((aRow + mi * 16) * KHS + kk + aK) * 2);
                ldm_x4(ah[mi][0], ah[mi][1], ah[mi][2], ah[mi][3],
                       sb + SM2_AH * 2 + off);
                ldm_x4(al[mi][0], al[mi][1], al[mi][2], al[mi][3],
                       sb + SM2_AL * 2 + off);
            }
            #pragma unroll
            for (int ni = 0; ni < 2; ni++) {
                uint32_t off =
                    (uint32_t)(((bRow + ni * 8) * KHS + kk + bK) * 2);
                ldm_x2(bh[ni][0], bh[ni][1], sb + SM2_BH * 2 + off);
                ldm_x2(bl2[ni][0], bl2[ni][1], sb + SM2_BL * 2 + off);
            }
            #pragma unroll
            for (int mi = 0; mi < 4; mi++)
                #pragma unroll
                for (int ni = 0; ni < 2; ni++) {
                    mma16816(acc[mi][ni], ah[mi][0], ah[mi][1], ah[mi][2],
                             ah[mi][3], bh[ni][0], bh[ni][1]);
                    mma16816(acc[mi][ni], ah[mi][0], ah[mi][1], ah[mi][2],
                             ah[mi][3], bl2[ni][0], bl2[ni][1]);
                    mma16816(acc[mi][ni], al[mi][0], al[mi][1], al[mi][2],
                             al[mi][3], bh[ni][0], bh[ni][1]);
                }
        }
        __syncthreads();  // all warps done reading B before next overwrite

        // ---- epilogue: 128x64 tile with bias ----
        const float* __restrict__ bias = z ? br : bl;
        float* __restrict__ out = z ? g_embR : g_embL;
        const int mbase = m0 + mw + (lane >> 2);
        #pragma unroll
        for (int ni = 0; ni < 2; ni++) {
            int col = nc * 64 + nwp + ni * 8 + (lane & 3) * 2;
            float2 bv = *(const float2*)(bias + col);
            #pragma unroll
            for (int mi = 0; mi < 4; mi++) {
                int mg0 = mbase + mi * 16;
                int mg1 = mg0 + 8;
                if (mg0 < cV) {
                    float2 o = make_float2(acc[mi][ni][0] + bv.x,
                                           acc[mi][ni][1] + bv.y);
                    *(float2*)(out + (size_t)mg0 * cD + col) = o;
                }
                if (mg1 < cV) {
                    float2 o = make_float2(acc[mi][ni][2] + bv.x,
                                           acc[mi][ni][3] + bv.y);
                    *(float2*)(out + (size_t)mg1 * cD + col) = o;
                }
            }
        }
    }
}

// ------------------------- K2: edge pass 1 (w) -------------------------
__global__ void __launch_bounds__(256) k_w(const int* __restrict__ eidx,
                                           const float* __restrict__ emb) {
    int gw = blockIdx.x * 8 + (threadIdx.x >> 5);
    int lane = threadIdx.x & 31;
    int g = gw / cE, e = gw % cE;
    int src = eidx[(g * 2) * cE + e];
    int dst = eidx[(g * 2 + 1) * cE + e];
    int ts = g_tok[g * cL + src];
    int td = g_tok[g * cL + dst];
    const float4* ra = (const float4*)(emb + (size_t)ts * cD);
    const float4* rb = (const float4*)(emb + (size_t)td * cD);
    float ss = 0.0f;
    #pragma unroll
    for (int i = 0; i < 2; i++) {
        int j = lane + i * 32;
        float4 a = ra[j], b = rb[j];
        float dx = a.x - b.x, dy = a.y - b.y, dz = a.z - b.z, dw = a.w - b.w;
        ss += dx * dx + dy * dy + dz * dz + dw * dw;
    }
    ss = warp_sum(ss);
    if (lane == 0) g_w[gw] = sqrtf(ss + 1e-12f);
}

// ------------------------- K3: beta -------------------------
__global__ void __launch_bounds__(256) k_beta() {
    int g = blockIdx.x, tid = threadIdx.x;
    __shared__ float sm[256];
    float s = 0.0f;
    for (int e = tid; e < cE; e += 256) s += g_w[g * cE + e];
    sm[tid] = s;
    __syncthreads();
    for (int o = 128; o > 0; o >>= 1) {
        if (tid < o) sm[tid] += sm[tid + o];
        __syncthreads();
    }
    if (tid == 0) g_beta[g] = sm[0] / (float)cE;
}

// ------------------------- K4: edge pass 2 (score) -------------------------
__global__ void __launch_bounds__(256) k_score(const int* __restrict__ eidx,
                                               const float* __restrict__ We,
                                               const float* __restrict__ att) {
    int gw = blockIdx.x * 8 + (threadIdx.x >> 5);
    int lane = threadIdx.x & 31;
    int g = gw / cE, e = gw % cE;
    int src = eidx[(g * 2) * cE + e];
    int dst = eidx[(g * 2 + 1) * cE + e];
    int ts = g_tok[g * cL + src];
    int td = g_tok[g * cL + dst];
    float w = g_w[gw];
    float bt = g_beta[g];
    float ew = expf(-(w * w) / (2.0f * bt * bt));
    const float4* rl = (const float4*)(g_embL + (size_t)ts * cD);
    const float4* rr = (const float4*)(g_embR + (size_t)td * cD);
    const float4* rw = (const float4*)We;
    const float4* ra = (const float4*)att;
    float s = 0.0f;
    #pragma unroll
    for (int i = 0; i < 2; i++) {
        int j = lane + i * 32;
        float4 a = rl[j], b = rr[j], c = rw[j], at = ra[j];
        float vx = a.x + b.x + ew * c.x;
        float vy = a.y + b.y + ew * c.y;
        float vz = a.z + b.z + ew * c.z;
        float vw = a.w + b.w + ew * c.w;
        vx = vx > 0.0f ? vx : 0.2f * vx;
        vy = vy > 0.0f ? vy : 0.2f * vy;
        vz = vz > 0.0f ? vz : 0.2f * vz;
        vw = vw > 0.0f ? vw : 0.2f * vw;
        s += vx * at.x + vy * at.y + vz * at.z + vw * at.w;
    }
    s = warp_sum(s);
    if (lane == 0) g_score[gw] = s;
}

// ------------------------- K5: segment softmax -------------------------
__global__ void __launch_bounds__(512) k_soft(const int* __restrict__ eidx) {
    int g = blockIdx.x, tid = threadIdx.x;
    __shared__ float m[cL];
    __shared__ float den[cL];
    m[tid] = -1e30f;
    den[tid] = 0.0f;
    __syncthreads();
    for (int e = tid; e < cE; e += 512) {
        int d = eidx[(g * 2 + 1) * cE + e];
        atomicMaxF(&m[d], g_score[g * cE + e]);
    }
    __syncthreads();
    for (int e = tid; e < cE; e += 512) {
        int d = eidx[(g * 2 + 1) * cE + e];
        float ex = expf(g_score[g * cE + e] - m[d]);
        g_alpha[g * cE + e] = ex;
        atomicAdd(&den[d], ex);
    }
    __syncthreads();
    for (int e = tid; e < cE; e += 512) {
        int d = eidx[(g * 2 + 1) * cE + e];
        g_alpha[g * cE + e] = g_alpha[g * cE + e] / (den[d] + 1e-16f);
    }
}

// ------------------------- K6: aggregate + max-pool -------------------------
__global__ void __launch_bounds__(256) k_agg(const int* __restrict__ eidx,
                                             const float* __restrict__ gat_bias) {
    int g = blockIdx.x, tid = threadIdx.x;
    __shared__ int cnt[cL];
    __shared__ int off[cL + 1];
    __shared__ int srow[cE];
    __shared__ float salpha[cE];

    for (int l = tid; l < cL; l += 256) cnt[l] = 0;
    __syncthreads();
    for (int e = tid; e < cE; e += 256) {
        int d = eidx[(g * 2 + 1) * cE + e];
        atomicAdd(&cnt[d], 1);
    }
    __syncthreads();
    if (tid == 0) {
        int run = 0;
        for (int l = 0; l < cL; l++) {
            off[l] = run;
            run += cnt[l];
            cnt[l] = 0;
        }
        off[cL] = run;
    }
    __syncthreads();
    for (int e = tid; e < cE; e += 256) {
        int d = eidx[(g * 2 + 1) * cE + e];
        int s = eidx[(g * 2) * cE + e];
        float a = g_alpha[g * cE + e];
        int tok = g_tok[g * cL + s];
        int pos = off[d] + atomicAdd(&cnt[d], 1);
        srow[pos] = tok;
        salpha[pos] = a;
    }
    __syncthreads();

    const int d = tid;
    const float bias = gat_bias[d];
    float pool = -1e30f;
    float acc = 0.0f;
    int cur = 0;
    int nxt = off[1];
    for (int base = 0; base < cE; base += 16) {
        float xv[16];
        #pragma unroll
        for (int j = 0; j < 16; j++)
            xv[j] = g_embL[(size_t)srow[base + j] * cD + d];
        #pragma unroll
        for (int j = 0; j < 16; j++) {
            int idx = base + j;
            while (idx >= nxt) {
                pool = fmaxf(pool, acc + bias);
                acc = 0.0f;
                cur++;
                nxt = off[cur + 1];
            }
            acc += salpha[idx] * xv[j];
        }
    }
    while (cur < cL) {
        pool = fmaxf(pool, acc + bias);
        acc = 0.0f;
        cur++;
    }
    g_pooled[g * cD + d] = pool;
}

// ------------------------- K7: GRU input gates -------------------------
__global__ void __launch_bounds__(256) k_gi(const float* __restrict__ Wihf,
                                            const float* __restrict__ bihf,
                                            const float* __restrict__ Wihb,
                                            const float* __restrict__ bihb) {
    int r = blockIdx.x;
    int dir = blockIdx.y;
    int tid = threadIdx.x;
    int t = r / cB, b = r % cB;
    int g = b * cT + t;
    const float* __restrict__ Wih = dir ? Wihb : Wihf;
    const float* __restrict__ bih = dir ? bihb : bihf;
    __shared__ float x[cD];
    x[tid] = g_pooled[g * cD + tid];
    __syncthreads();
    const float4* xv = (const float4*)x;
    #pragma unroll
    for (int q = 0; q < 3; q++) {
        int j = q * 256 + tid;
        float s = bih[j];
        const float4* wr = (const float4*)(Wih + (size_t)j * cD);
        #pragma unroll 8
        for (int k4 = 0; k4 < 64; k4++) {
            float4 wv = wr[k4];
            float4 xx = xv[k4];
            s += wv.x * xx.x + wv.y * xx.y + wv.z * xx.z + wv.w * xx.w;
        }
        g_gi[dir][(size_t)r * 768 + j] = s;
    }
}

// ------------------------- K8: GRU step -------------------------
__global__ void __launch_bounds__(256) k_step(int step,
                                              const float* __restrict__ Whhf,
                                              const float* __restrict__ bhhf,
                                              const float* __restrict__ Whhb,
                                              const float* __restrict__ bhhb) {
    const int dir = blockIdx.y;
    const int t = (dir == 0) ? step : (cT - 1 - step);
    const int pin = step & 1, pout = (step + 1) & 1;
    const int tid = threadIdx.x;
    const int b = tid & 15;
    const int jt = tid >> 4;
    const int i = blockIdx.x * 16 + jt;

    const float* __restrict__ Whh = dir ? Whhb : Whhf;
    const float* __restrict__ bhh = dir ? bhhb : bhhf;

    __shared__ float h[cB * cH];
    for (int idx = tid; idx < cB * cH; idx += 256) h[idx] = g_h[dir][pin][idx];
    __syncthreads();

    const float4* hv = (const float4*)(h + b * cH);
    const float4* w0 = (const float4*)(Whh + (size_t)i * cD);
    const float4* w1 = (const float4*)(Whh + (size_t)(i + 256) * cD);
    const float4* w2 = (const float4*)(Whh + (size_t)(i + 512) * cD);
    float hr = 0.0f, hz = 0.0f, hn = 0.0f;
    #pragma unroll 4
    for (int k4 = 0; k4 < 64; k4++) {
        float4 hh = hv[k4];
        float4 a = w0[k4], c = w1[k4], d = w2[k4];
        hr += a.x * hh.x + a.y * hh.y + a.z * hh.z + a.w * hh.w;
        hz += c.x * hh.x + c.y * hh.y + c.z * hh.z + c.w * hh.w;
        hn += d.x * hh.x + d.y * hh.y + d.z * hh.z + d.w * hh.w;
    }
    hr += bhh[i];
    hz += bhh[i + 256];
    hn += bhh[i + 512];

    const float* gi = &g_gi[dir][(size_t)(t * cB + b) * 768];
    float r = sigmoidf_(gi[i] + hr);
    float z = sigmoidf_(gi[i + 256] + hz);
    float n = tanhf(gi[i + 512] + r * hn);
    float hp = h[b * cH + i];
    float hnew = (1.0f - z) * n + z * hp;

    g_ys[dir][(size_t)(t * cB + b) * cH + i] = hnew;
    g_h[dir][pout][b * cH + i] = hnew;
}

// ------------------------- K9: finalize output -------------------------
__global__ void __launch_bounds__(256) k_fin(float* __restrict__ out) {
    int idx = blockIdx.x * 256 + threadIdx.x;
    const int n1 = cT * cB * cH;
    const int n2 = n1 + cB * cH;
    if (idx < n1) {
        out[idx] = g_ys[0][idx] + g_ys[1][idx];
    } else if (idx < n2) {
        out[idx] = g_ys[0][(cT - 1) * cB * cH + (idx - n1)];
    } else {
        out[idx] = g_ys[1][idx - n2];
    }
}

// ------------------------- launch -------------------------
extern "C" void kernel_launch(void* const* d_in, const int* in_sizes, int n_in,
                              void* d_out, int out_size) {
    const int*   token_ids = (const int*)d_in[0];
    const int*   edge_index = (const int*)d_in[1];
    const float* emb  = (const float*)d_in[2];
    const float* Wl   = (const float*)d_in[3];
    const float* bl   = (const float*)d_in[4];
    const float* Wr   = (const float*)d_in[5];
    const float* br   = (const float*)d_in[6];
    const float* We   = (const float*)d_in[7];
    const float* att  = (const float*)d_in[8];
    const float* gbias = (const float*)d_in[9];
    const float* Wihf = (const float*)d_in[10];
    const float* Whhf = (const float*)d_in[11];
    const float* bihf = (const float*)d_in[12];
    const float* bhhf = (const float*)d_in[13];
    const float* Wihb = (const float*)d_in[14];
    const float* Whhb = (const float*)d_in[15];
    const float* bihb = (const float*)d_in[16];
    const float* bhhb = (const float*)d_in[17];
    float* out = (float*)d_out;

    cudaFuncSetAttribute(k_gemm2,
                         cudaFuncAttributeMaxDynamicSharedMemorySize, SMEM2);

    k_tok<<<cG, cL>>>(token_ids);
    k_zero<<<64, 256>>>();
    k_splitA<<<(int)(((size_t)cVp * cD) / (256 * 8)), 256>>>(emb);
    k_splitB<<<dim3(cD, 2), cD>>>(Wl, Wr);
    k_gemm2<<<cVp / 128, 256, SMEM2>>>(bl, br);
    k_w<<<cG * cE / 8, 256>>>(edge_index, emb);
    k_beta<<<cG, 256>>>();
    k_score<<<cG * cE / 8, 256>>>(edge_index, We, att);
    k_soft<<<cG, 512>>>(edge_index);
    k_agg<<<cG, 256>>>(edge_index, gbias);
    k_gi<<<dim3(cT * cB, 2), 256>>>(Wihf, bihf, Wihb, bihb);
    for (int step = 0; step < cT; step++)
        k_step<<<dim3(16, 2), 256>>>(step, Whhf, bhhf, Whhb, bhhb);
    k_fin<<<160, 256>>>(out);
}

// round 6
// speedup vs baseline: 1.6235x; 1.2632x over previous
#include <cuda_runtime.h>
#include <cuda_bf16.h>
#include <cstdint>
#include <math.h>

// Problem constants (fixed by the dataset)
constexpr int cV = 50000;   // vocab
constexpr int cVp = 50048;  // vocab padded to 391*128
constexpr int cD = 256;     // embedding dim
constexpr int cH = 256;     // GRU hidden
constexpr int cB = 16;      // batch
constexpr int cT = 8;       // num_subtrees (time steps)
constexpr int cL = 512;     // subtree_len (nodes per graph)
constexpr int cE = 2048;    // edges per graph
constexpr int cG = cB * cT; // graphs = 128

// ------------------------- device scratch -------------------------
__device__ float g_embL[(size_t)cV * cD];   // emb_table @ Wl + bl
__device__ float g_embR[(size_t)cV * cD];   // emb_table @ Wr + br
__device__ __nv_bfloat16 g_Ahi[(size_t)cVp * cD];
__device__ __nv_bfloat16 g_Alo[(size_t)cVp * cD];
__device__ __nv_bfloat16 g_Bhi[2][cD * cD];  // W^T split hi: [z][n][k]
__device__ __nv_bfloat16 g_Blo[2][cD * cD];
__device__ int   g_tok[cG * cL];
__device__ float g_w[cG * cE];
__device__ float g_beta[cG];
__device__ float g_pooled[cG * cD];
__device__ float g_gi[2][cT * cB * 3 * cH];
__device__ float g_h[2][2][cB * cH];        // [dir][parity][b*H]
__device__ float g_ys[2][cT * cB * cH];

// ------------------------- small utils -------------------------
__device__ __forceinline__ float warp_sum(float v) {
    #pragma unroll
    for (int o = 16; o > 0; o >>= 1) v += __shfl_xor_sync(0xffffffffu, v, o);
    return v;
}
__device__ __forceinline__ void atomicMaxF(float* addr, float val) {
    int* ia = (int*)addr;
    int old = __float_as_int(*addr);
    while (__int_as_float(old) < val) {
        int prev = atomicCAS(ia, old, __float_as_int(val));
        if (prev == old) break;
        old = prev;
    }
}
__device__ __forceinline__ float sigmoidf_(float x) { return 1.0f / (1.0f + expf(-x)); }

// ------------------------- mma.sync helpers -------------------------
__device__ __forceinline__ uint32_t smem_u32(const void* p) {
    uint32_t a;
    asm("{ .reg .u64 t; cvta.to.shared.u64 t, %1; cvt.u32.u64 %0, t; }"
        : "=r"(a) : "l"(p));
    return a;
}
__device__ __forceinline__ void ldm_x4(uint32_t& r0, uint32_t& r1, uint32_t& r2,
                                       uint32_t& r3, uint32_t addr) {
    asm volatile("ldmatrix.sync.aligned.m8n8.x4.shared.b16 {%0,%1,%2,%3}, [%4];"
                 : "=r"(r0), "=r"(r1), "=r"(r2), "=r"(r3) : "r"(addr));
}
__device__ __forceinline__ void ldm_x2(uint32_t& r0, uint32_t& r1, uint32_t addr) {
    asm volatile("ldmatrix.sync.aligned.m8n8.x2.shared.b16 {%0,%1}, [%2];"
                 : "=r"(r0), "=r"(r1) : "r"(addr));
}
__device__ __forceinline__ void mma16816(float* d, uint32_t a0, uint32_t a1,
                                         uint32_t a2, uint32_t a3,
                                         uint32_t b0, uint32_t b1) {
    asm volatile(
        "mma.sync.aligned.m16n8k16.row.col.f32.bf16.bf16.f32 "
        "{%0,%1,%2,%3}, {%4,%5,%6,%7}, {%8,%9}, {%0,%1,%2,%3};"
        : "+f"(d[0]), "+f"(d[1]), "+f"(d[2]), "+f"(d[3])
        : "r"(a0), "r"(a1), "r"(a2), "r"(a3), "r"(b0), "r"(b1));
}
__device__ __forceinline__ void cpa16(uint32_t dst, const void* src) {
    asm volatile("cp.async.cg.shared.global [%0], [%1], 16;" :: "r"(dst),
                 "l"(src));
}
__device__ __forceinline__ void cpa_commit() {
    asm volatile("cp.async.commit_group;" ::: "memory");
}
__device__ __forceinline__ void cpa_wait0() {
    asm volatile("cp.async.wait_group 0;" ::: "memory");
}

// ------------------------- K0: token LUT -------------------------
__global__ void k_tok(const int* __restrict__ token_ids) {
    int g = blockIdx.x, l = threadIdx.x;
    int b = g / cT, t = g % cT;
    g_tok[g * cL + l] = token_ids[(t * cL + l) * cB + b];
}

__global__ void k_zero() {
    int idx = blockIdx.x * 256 + threadIdx.x;
    ((float*)g_h)[idx] = 0.0f;
}

// ------------------------- split-precision conversion -------------------------
__global__ void __launch_bounds__(256) k_splitA(const float* __restrict__ emb) {
    size_t idx = ((size_t)blockIdx.x * 256 + threadIdx.x) * 8;
    int row = (int)(idx >> 8);
    float v[8];
    if (row < cV) {
        float4 a = *(const float4*)(emb + idx);
        float4 b = *(const float4*)(emb + idx + 4);
        v[0] = a.x; v[1] = a.y; v[2] = a.z; v[3] = a.w;
        v[4] = b.x; v[5] = b.y; v[6] = b.z; v[7] = b.w;
    } else {
        #pragma unroll
        for (int i = 0; i < 8; i++) v[i] = 0.0f;
    }
    __nv_bfloat16 hi[8], lo[8];
    #pragma unroll
    for (int i = 0; i < 8; i++) {
        hi[i] = __float2bfloat16_rn(v[i]);
        lo[i] = __float2bfloat16_rn(v[i] - __bfloat162float(hi[i]));
    }
    *(uint4*)(g_Ahi + idx) = *(uint4*)hi;
    *(uint4*)(g_Alo + idx) = *(uint4*)lo;
}

// W -> W^T hi/lo bf16 (B operand is [n][k], K-contiguous)
__global__ void __launch_bounds__(256) k_splitB(const float* __restrict__ Wl,
                                                const float* __restrict__ Wr) {
    int z = blockIdx.y, n = blockIdx.x, k = threadIdx.x;
    const float* W = z ? Wr : Wl;
    float x = W[(size_t)k * cD + n];
    __nv_bfloat16 hi = __float2bfloat16_rn(x);
    __nv_bfloat16 lo = __float2bfloat16_rn(x - __bfloat162float(hi));
    g_Bhi[z][n * cD + k] = hi;
    g_Blo[z][n * cD + k] = lo;
}

// ------------------------- K1: mma.sync bf16 split GEMM (A-resident) ------
constexpr int KHS = 264;  // halves per smem row (528 B, pad 8)
constexpr int SM2_AH = 0;
constexpr int SM2_AL = 128 * KHS;
constexpr int SM2_BH = 2 * 128 * KHS;
constexpr int SM2_BL = 2 * 128 * KHS + 64 * KHS;
constexpr int SMEM2 = (2 * 128 * KHS + 2 * 64 * KHS) * 2;  // 202752 B

__global__ void __launch_bounds__(256, 1)
k_gemm2(const float* __restrict__ bl, const float* __restrict__ br) {
    extern __shared__ __nv_bfloat16 sm2[];
    const uint32_t sb = smem_u32(sm2);
    const int tid = threadIdx.x, wid = tid >> 5, lane = tid & 31;
    const int m0 = blockIdx.x * 128;

    #pragma unroll
    for (int i = 0; i < 16; i++) {
        int idx = tid + i * 256;
        int r = idx >> 5, c = idx & 31;
        size_t gs = (size_t)(m0 + r) * cD + c * 8;
        uint32_t d = (uint32_t)((r * KHS + c * 8) * 2);
        cpa16(sb + SM2_AH * 2 + d, g_Ahi + gs);
        cpa16(sb + SM2_AL * 2 + d, g_Alo + gs);
    }
    cpa_commit();

    const int mw = (wid & 1) * 64;
    const int nwp = (wid >> 1) * 16;
    const int aRow = mw + (lane & 15);
    const int aK = (lane >> 4) * 8;
    const int bRow = nwp + (lane & 7);
    const int bK = ((lane >> 3) & 1) * 8;

    #pragma unroll 1
    for (int iter = 0; iter < 8; iter++) {
        const int z = iter >> 2, nc = iter & 3;
        const __nv_bfloat16* __restrict__ gBh = g_Bhi[z];
        const __nv_bfloat16* __restrict__ gBl = g_Blo[z];

        #pragma unroll
        for (int i = 0; i < 8; i++) {
            int idx = tid + i * 256;
            int r = idx >> 5, c = idx & 31;
            size_t gs = (size_t)(nc * 64 + r) * cD + c * 8;
            uint32_t d = (uint32_t)((r * KHS + c * 8) * 2);
            cpa16(sb + SM2_BH * 2 + d, gBh + gs);
            cpa16(sb + SM2_BL * 2 + d, gBl + gs);
        }
        cpa_commit();
        cpa_wait0();
        __syncthreads();

        float acc[4][2][4];
        #pragma unroll
        for (int mi = 0; mi < 4; mi++)
            #pragma unroll
            for (int ni = 0; ni < 2; ni++)
                #pragma unroll
                for (int q = 0; q < 4; q++) acc[mi][ni][q] = 0.0f;

        #pragma unroll 4
        for (int ks = 0; ks < 16; ks++) {
            const int kk = ks * 16;
            uint32_t ah[4][4], al[4][4], bh[2][2], bl2[2][2];
            #pragma unroll
            for (int mi = 0; mi < 4; mi++) {
                uint32_t off =
                    (uint32_t)(((aRow + mi * 16) * KHS + kk + aK) * 2);
                ldm_x4(ah[mi][0], ah[mi][1], ah[mi][2], ah[mi][3],
                       sb + SM2_AH * 2 + off);
                ldm_x4(al[mi][0], al[mi][1], al[mi][2], al[mi][3],
                       sb + SM2_AL * 2 + off);
            }
            #pragma unroll
            for (int ni = 0; ni < 2; ni++) {
                uint32_t off =
                    (uint32_t)(((bRow + ni * 8) * KHS + kk + bK) * 2);
                ldm_x2(bh[ni][0], bh[ni][1], sb + SM2_BH * 2 + off);
                ldm_x2(bl2[ni][0], bl2[ni][1], sb + SM2_BL * 2 + off);
            }
            #pragma unroll
            for (int mi = 0; mi < 4; mi++)
                #pragma unroll
                for (int ni = 0; ni < 2; ni++) {
                    mma16816(acc[mi][ni], ah[mi][0], ah[mi][1], ah[mi][2],
                             ah[mi][3], bh[ni][0], bh[ni][1]);
                    mma16816(acc[mi][ni], ah[mi][0], ah[mi][1], ah[mi][2],
                             ah[mi][3], bl2[ni][0], bl2[ni][1]);
                    mma16816(acc[mi][ni], al[mi][0], al[mi][1], al[mi][2],
                             al[mi][3], bh[ni][0], bh[ni][1]);
                }
        }
        __syncthreads();

        const float* __restrict__ bias = z ? br : bl;
        float* __restrict__ out = z ? g_embR : g_embL;
        const int mbase = m0 + mw + (lane >> 2);
        #pragma unroll
        for (int ni = 0; ni < 2; ni++) {
            int col = nc * 64 + nwp + ni * 8 + (lane & 3) * 2;
            float2 bv = *(const float2*)(bias + col);
            #pragma unroll
            for (int mi = 0; mi < 4; mi++) {
                int mg0 = mbase + mi * 16;
                int mg1 = mg0 + 8;
                if (mg0 < cV) {
                    float2 o = make_float2(acc[mi][ni][0] + bv.x,
                                           acc[mi][ni][1] + bv.y);
                    *(float2*)(out + (size_t)mg0 * cD + col) = o;
                }
                if (mg1 < cV) {
                    float2 o = make_float2(acc[mi][ni][2] + bv.x,
                                           acc[mi][ni][3] + bv.y);
                    *(float2*)(out + (size_t)mg1 * cD + col) = o;
                }
            }
        }
    }
}

// ------------------------- K2: edge pass 1 (w), 2 edges/warp -------------------------
__global__ void __launch_bounds__(256) k_w(const int* __restrict__ eidx,
                                           const float* __restrict__ emb) {
    int wrp = blockIdx.x * 8 + (threadIdx.x >> 5);
    int lane = threadIdx.x & 31;
    int gw0 = wrp * 2;            // edges gw0, gw0+1 (same graph: cE even)
    int g = gw0 / cE;
    int e0 = gw0 % cE;
    const int* __restrict__ srcb = eidx + (size_t)(g * 2) * cE;
    const int* __restrict__ dstb = srcb + cE;
    int s0 = srcb[e0], s1 = srcb[e0 + 1];
    int d0 = dstb[e0], d1 = dstb[e0 + 1];
    int ts0 = g_tok[g * cL + s0], ts1 = g_tok[g * cL + s1];
    int td0 = g_tok[g * cL + d0], td1 = g_tok[g * cL + d1];
    const float4* a0p = (const float4*)(emb + (size_t)ts0 * cD);
    const float4* b0p = (const float4*)(emb + (size_t)td0 * cD);
    const float4* a1p = (const float4*)(emb + (size_t)ts1 * cD);
    const float4* b1p = (const float4*)(emb + (size_t)td1 * cD);
    float ss0 = 0.0f, ss1 = 0.0f;
    #pragma unroll
    for (int i = 0; i < 2; i++) {
        int j = lane + i * 32;
        float4 a0 = a0p[j], b0 = b0p[j], a1 = a1p[j], b1 = b1p[j];
        float x0 = a0.x - b0.x, y0 = a0.y - b0.y, z0 = a0.z - b0.z,
              w0 = a0.w - b0.w;
        float x1 = a1.x - b1.x, y1 = a1.y - b1.y, z1 = a1.z - b1.z,
              w1 = a1.w - b1.w;
        ss0 += x0 * x0 + y0 * y0 + z0 * z0 + w0 * w0;
        ss1 += x1 * x1 + y1 * y1 + z1 * z1 + w1 * w1;
    }
    ss0 = warp_sum(ss0);
    ss1 = warp_sum(ss1);
    if (lane == 0) {
        g_w[gw0] = sqrtf(ss0 + 1e-12f);
        g_w[gw0 + 1] = sqrtf(ss1 + 1e-12f);
    }
}

// ------------------------- K3: beta -------------------------
__global__ void __launch_bounds__(256) k_beta() {
    int g = blockIdx.x, tid = threadIdx.x;
    __shared__ float sm[256];
    float s = 0.0f;
    for (int e = tid; e < cE; e += 256) s += g_w[g * cE + e];
    sm[tid] = s;
    __syncthreads();
    for (int o = 128; o > 0; o >>= 1) {
        if (tid < o) sm[tid] += sm[tid + o];
        __syncthreads();
    }
    if (tid == 0) g_beta[g] = sm[0] / (float)cE;
}

// ------------------------- K4: fused GAT (score+softmax+agg+pool) ----------
// One block per graph, 512 threads = 16 warps. CSR by dst in smem, then one
// warp per dst doing online softmax over its incoming edges; xl rows read
// exactly once per edge. Pool-max folded via register max + smem atomicMax.
__global__ void __launch_bounds__(512) k_gat(const int* __restrict__ eidx,
                                             const float* __restrict__ We,
                                             const float* __restrict__ att,
                                             const float* __restrict__ gbias) {
    const int g = blockIdx.x;
    const int tid = threadIdx.x, lane = tid & 31, wrp = tid >> 5;
    __shared__ int off[cL + 1];
    __shared__ int cnt[cL];
    __shared__ int etok[cE];
    __shared__ float eew[cE];
    __shared__ float spool[cD];

    for (int i = tid; i < cL; i += 512) cnt[i] = 0;
    if (tid < cD) spool[tid] = -1e30f;
    __syncthreads();
    for (int e = tid; e < cE; e += 512) {
        int d = eidx[(size_t)(g * 2 + 1) * cE + e];
        atomicAdd(&cnt[d], 1);
    }
    __syncthreads();
    // inclusive scan of cnt into off[1..512]; off[0]=0
    if (tid == 0) off[0] = 0;
    off[tid + 1] = cnt[tid];
    __syncthreads();
    #pragma unroll
    for (int st = 1; st < cL; st <<= 1) {
        int v = off[tid + 1];
        if (tid >= st) v += off[tid + 1 - st];
        __syncthreads();
        off[tid + 1] = v;
        __syncthreads();
    }
    cnt[tid] = 0;
    __syncthreads();
    // scatter: CSR payload = src token + edge weight ew
    {
        float beta = g_beta[g];
        float c = -0.5f / (beta * beta);
        for (int e = tid; e < cE; e += 512) {
            int d = eidx[(size_t)(g * 2 + 1) * cE + e];
            int s = eidx[(size_t)(g * 2) * cE + e];
            int pos = off[d] + atomicAdd(&cnt[d], 1);
            etok[pos] = g_tok[g * cL + s];
            float w = g_w[g * cE + e];
            eew[pos] = expf(w * w * c);
        }
    }
    __syncthreads();

    // per-warp dst loop
    const int q0 = lane * 4, q1 = 128 + lane * 4;
    const float4 We0 = *(const float4*)(We + q0);
    const float4 We1 = *(const float4*)(We + q1);
    const float4 at0 = *(const float4*)(att + q0);
    const float4 at1 = *(const float4*)(att + q1);
    const float4 gb0 = *(const float4*)(gbias + q0);
    const float4 gb1 = *(const float4*)(gbias + q1);
    float4 pm0 = make_float4(-1e30f, -1e30f, -1e30f, -1e30f);
    float4 pm1 = pm0;

    for (int dst = wrp; dst < cL; dst += 16) {
        int tokd = g_tok[g * cL + dst];
        const float4 xr0 = *(const float4*)(g_embR + (size_t)tokd * cD + q0);
        const float4 xr1 = *(const float4*)(g_embR + (size_t)tokd * cD + q1);
        float m = -1e30f, den = 0.0f;
        float4 a0 = make_float4(0.f, 0.f, 0.f, 0.f), a1 = a0;
        const int pend = off[dst + 1];
        for (int p = off[dst]; p < pend; p++) {
            int tok = etok[p];
            float ew = eew[p];
            const float4 x0 = *(const float4*)(g_embL + (size_t)tok * cD + q0);
            const float4 x1 = *(const float4*)(g_embL + (size_t)tok * cD + q1);
            float vx, par = 0.0f;
            vx = x0.x + xr0.x + ew * We0.x; par += (vx > 0.f ? vx : 0.2f * vx) * at0.x;
            vx = x0.y + xr0.y + ew * We0.y; par += (vx > 0.f ? vx : 0.2f * vx) * at0.y;
            vx = x0.z + xr0.z + ew * We0.z; par += (vx > 0.f ? vx : 0.2f * vx) * at0.z;
            vx = x0.w + xr0.w + ew * We0.w; par += (vx > 0.f ? vx : 0.2f * vx) * at0.w;
            vx = x1.x + xr1.x + ew * We1.x; par += (vx > 0.f ? vx : 0.2f * vx) * at1.x;
            vx = x1.y + xr1.y + ew * We1.y; par += (vx > 0.f ? vx : 0.2f * vx) * at1.y;
            vx = x1.z + xr1.z + ew * We1.z; par += (vx > 0.f ? vx : 0.2f * vx) * at1.z;
            vx = x1.w + xr1.w + ew * We1.w; par += (vx > 0.f ? vx : 0.2f * vx) * at1.w;
            float s = warp_sum(par);
            float mn = fmaxf(m, s);
            float sc = __expf(m - mn);   // m=-inf first iter -> 0
            float pe = __expf(s - mn);
            den = den * sc + pe;
            a0.x = a0.x * sc + pe * x0.x; a0.y = a0.y * sc + pe * x0.y;
            a0.z = a0.z * sc + pe * x0.z; a0.w = a0.w * sc + pe * x0.w;
            a1.x = a1.x * sc + pe * x1.x; a1.y = a1.y * sc + pe * x1.y;
            a1.z = a1.z * sc + pe * x1.z; a1.w = a1.w * sc + pe * x1.w;
            m = mn;
        }
        float inv = 1.0f / (den + 1e-16f);
        pm0.x = fmaxf(pm0.x, a0.x * inv + gb0.x);
        pm0.y = fmaxf(pm0.y, a0.y * inv + gb0.y);
        pm0.z = fmaxf(pm0.z, a0.z * inv + gb0.z);
        pm0.w = fmaxf(pm0.w, a0.w * inv + gb0.w);
        pm1.x = fmaxf(pm1.x, a1.x * inv + gb1.x);
        pm1.y = fmaxf(pm1.y, a1.y * inv + gb1.y);
        pm1.z = fmaxf(pm1.z, a1.z * inv + gb1.z);
        pm1.w = fmaxf(pm1.w, a1.w * inv + gb1.w);
    }
    atomicMaxF(&spool[q0 + 0], pm0.x);
    atomicMaxF(&spool[q0 + 1], pm0.y);
    atomicMaxF(&spool[q0 + 2], pm0.z);
    atomicMaxF(&spool[q0 + 3], pm0.w);
    atomicMaxF(&spool[q1 + 0], pm1.x);
    atomicMaxF(&spool[q1 + 1], pm1.y);
    atomicMaxF(&spool[q1 + 2], pm1.z);
    atomicMaxF(&spool[q1 + 3], pm1.w);
    __syncthreads();
    if (tid < cD) g_pooled[g * cD + tid] = spool[tid];
}

// ------------------------- K7: GRU input gates -------------------------
__global__ void __launch_bounds__(256) k_gi(const float* __restrict__ Wihf,
                                            const float* __restrict__ bihf,
                                            const float* __restrict__ Wihb,
                                            const float* __restrict__ bihb) {
    int r = blockIdx.x;
    int dir = blockIdx.y;
    int tid = threadIdx.x;
    int t = r / cB, b = r % cB;
    int g = b * cT + t;
    const float* __restrict__ Wih = dir ? Wihb : Wihf;
    const float* __restrict__ bih = dir ? bihb : bihf;
    __shared__ float x[cD];
    x[tid] = g_pooled[g * cD + tid];
    __syncthreads();
    const float4* xv = (const float4*)x;
    #pragma unroll
    for (int q = 0; q < 3; q++) {
        int j = q * 256 + tid;
        float s = bih[j];
        const float4* wr = (const float4*)(Wih + (size_t)j * cD);
        #pragma unroll 8
        for (int k4 = 0; k4 < 64; k4++) {
            float4 wv = wr[k4];
            float4 xx = xv[k4];
            s += wv.x * xx.x + wv.y * xx.y + wv.z * xx.z + wv.w * xx.w;
        }
        g_gi[dir][(size_t)r * 768 + j] = s;
    }
}

// ------------------------- K8: GRU step -------------------------
__global__ void __launch_bounds__(256) k_step(int step,
                                              const float* __restrict__ Whhf,
                                              const float* __restrict__ bhhf,
                                              const float* __restrict__ Whhb,
                                              const float* __restrict__ bhhb) {
    const int dir = blockIdx.y;
    const int t = (dir == 0) ? step : (cT - 1 - step);
    const int pin = step & 1, pout = (step + 1) & 1;
    const int tid = threadIdx.x;
    const int b = tid & 15;
    const int jt = tid >> 4;
    const int i = blockIdx.x * 16 + jt;

    const float* __restrict__ Whh = dir ? Whhb : Whhf;
    const float* __restrict__ bhh = dir ? bhhb : bhhf;

    __shared__ float h[cB * cH];
    for (int idx = tid; idx < cB * cH; idx += 256) h[idx] = g_h[dir][pin][idx];
    __syncthreads();

    const float4* hv = (const float4*)(h + b * cH);
    const float4* w0 = (const float4*)(Whh + (size_t)i * cD);
    const float4* w1 = (const float4*)(Whh + (size_t)(i + 256) * cD);
    const float4* w2 = (const float4*)(Whh + (size_t)(i + 512) * cD);
    float hr = 0.0f, hz = 0.0f, hn = 0.0f;
    #pragma unroll 4
    for (int k4 = 0; k4 < 64; k4++) {
        float4 hh = hv[k4];
        float4 a = w0[k4], c = w1[k4], d = w2[k4];
        hr += a.x * hh.x + a.y * hh.y + a.z * hh.z + a.w * hh.w;
        hz += c.x * hh.x + c.y * hh.y + c.z * hh.z + c.w * hh.w;
        hn += d.x * hh.x + d.y * hh.y + d.z * hh.z + d.w * hh.w;
    }
    hr += bhh[i];
    hz += bhh[i + 256];
    hn += bhh[i + 512];

    const float* gi = &g_gi[dir][(size_t)(t * cB + b) * 768];
    float r = sigmoidf_(gi[i] + hr);
    float z = sigmoidf_(gi[i + 256] + hz);
    float n = tanhf(gi[i + 512] + r * hn);
    float hp = h[b * cH + i];
    float hnew = (1.0f - z) * n + z * hp;

    g_ys[dir][(size_t)(t * cB + b) * cH + i] = hnew;
    g_h[dir][pout][b * cH + i] = hnew;
}

// ------------------------- K9: finalize output -------------------------
__global__ void __launch_bounds__(256) k_fin(float* __restrict__ out) {
    int idx = blockIdx.x * 256 + threadIdx.x;
    const int n1 = cT * cB * cH;
    const int n2 = n1 + cB * cH;
    if (idx < n1) {
        out[idx] = g_ys[0][idx] + g_ys[1][idx];
    } else if (idx < n2) {
        out[idx] = g_ys[0][(cT - 1) * cB * cH + (idx - n1)];
    } else {
        out[idx] = g_ys[1][idx - n2];
    }
}

// ------------------------- launch -------------------------
extern "C" void kernel_launch(void* const* d_in, const int* in_sizes, int n_in,
                              void* d_out, int out_size) {
    const int*   token_ids = (const int*)d_in[0];
    const int*   edge_index = (const int*)d_in[1];
    const float* emb  = (const float*)d_in[2];
    const float* Wl   = (const float*)d_in[3];
    const float* bl   = (const float*)d_in[4];
    const float* Wr   = (const float*)d_in[5];
    const float* br   = (const float*)d_in[6];
    const float* We   = (const float*)d_in[7];
    const float* att  = (const float*)d_in[8];
    const float* gbias = (const float*)d_in[9];
    const float* Wihf = (const float*)d_in[10];
    const float* Whhf = (const float*)d_in[11];
    const float* bihf = (const float*)d_in[12];
    const float* bhhf = (const float*)d_in[13];
    const float* Wihb = (const float*)d_in[14];
    const float* Whhb = (const float*)d_in[15];
    const float* bihb = (const float*)d_in[16];
    const float* bhhb = (const float*)d_in[17];
    float* out = (float*)d_out;

    cudaFuncSetAttribute(k_gemm2,
                         cudaFuncAttributeMaxDynamicSharedMemorySize, SMEM2);

    k_tok<<<cG, cL>>>(token_ids);
    k_zero<<<64, 256>>>();
    k_splitA<<<(int)(((size_t)cVp * cD) / (256 * 8)), 256>>>(emb);
    k_splitB<<<dim3(cD, 2), cD>>>(Wl, Wr);
    k_gemm2<<<cVp / 128, 256, SMEM2>>>(bl, br);
    k_w<<<cG * cE / 16, 256>>>(edge_index, emb);
    k_beta<<<cG, 256>>>();
    k_gat<<<cG, 512>>>(edge_index, We, att, gbias);
    k_gi<<<dim3(cT * cB, 2), 256>>>(Wihf, bihf, Wihb, bihb);
    for (int step = 0; step < cT; step++)
        k_step<<<dim3(16, 2), 256>>>(step, Whhf, bhhf, Whhb, bhhb);
    k_fin<<<160, 256>>>(out);
}

// round 7
// speedup vs baseline: 1.7959x; 1.1062x over previous
#include <cuda_runtime.h>
#include <cuda_bf16.h>
#include <cstdint>
#include <math.h>

// Problem constants (fixed by the dataset)
constexpr int cV = 50000;   // vocab
constexpr int cVp = 50048;  // vocab padded to 391*128
constexpr int cD = 256;     // embedding dim
constexpr int cH = 256;     // GRU hidden
constexpr int cB = 16;      // batch
constexpr int cT = 8;       // num_subtrees (time steps)
constexpr int cL = 512;     // subtree_len (nodes per graph)
constexpr int cE = 2048;    // edges per graph
constexpr int cG = cB * cT; // graphs = 128

// ------------------------- device scratch -------------------------
__device__ float g_embL[(size_t)cV * cD];   // emb_table @ Wl + bl
__device__ float g_embR[(size_t)cV * cD];   // emb_table @ Wr + br
__device__ __nv_bfloat16 g_Ahi[(size_t)cVp * cD];
__device__ __nv_bfloat16 g_Alo[(size_t)cVp * cD];
__device__ __nv_bfloat16 g_Bhi[2][cD * cD];  // W^T split hi: [z][n][k]
__device__ __nv_bfloat16 g_Blo[2][cD * cD];
__device__ int   g_tok[cG * cL];
__device__ float g_w[cG * cE];
__device__ float g_beta[cG];
__device__ float g_pooled[cG * cD];
__device__ float g_gi[2][cT * cB * 3 * cH];
__device__ float g_h[2][2][cB * cH];        // [dir][parity][b*H]
__device__ float g_ys[2][cT * cB * cH];
__device__ unsigned g_grubar[2];            // GRU inter-CTA barrier tickets

// ------------------------- small utils -------------------------
__device__ __forceinline__ float warp_sum(float v) {
    #pragma unroll
    for (int o = 16; o > 0; o >>= 1) v += __shfl_xor_sync(0xffffffffu, v, o);
    return v;
}
__device__ __forceinline__ void atomicMaxF(float* addr, float val) {
    int* ia = (int*)addr;
    int old = __float_as_int(*addr);
    while (__int_as_float(old) < val) {
        int prev = atomicCAS(ia, old, __float_as_int(val));
        if (prev == old) break;
        old = prev;
    }
}
__device__ __forceinline__ float sigmoidf_(float x) { return 1.0f / (1.0f + expf(-x)); }

// ------------------------- mma.sync helpers -------------------------
__device__ __forceinline__ uint32_t smem_u32(const void* p) {
    uint32_t a;
    asm("{ .reg .u64 t; cvta.to.shared.u64 t, %1; cvt.u32.u64 %0, t; }"
        : "=r"(a) : "l"(p));
    return a;
}
__device__ __forceinline__ void ldm_x4(uint32_t& r0, uint32_t& r1, uint32_t& r2,
                                       uint32_t& r3, uint32_t addr) {
    asm volatile("ldmatrix.sync.aligned.m8n8.x4.shared.b16 {%0,%1,%2,%3}, [%4];"
                 : "=r"(r0), "=r"(r1), "=r"(r2), "=r"(r3) : "r"(addr));
}
__device__ __forceinline__ void ldm_x2(uint32_t& r0, uint32_t& r1, uint32_t addr) {
    asm volatile("ldmatrix.sync.aligned.m8n8.x2.shared.b16 {%0,%1}, [%2];"
                 : "=r"(r0), "=r"(r1) : "r"(addr));
}
__device__ __forceinline__ void mma16816(float* d, uint32_t a0, uint32_t a1,
                                         uint32_t a2, uint32_t a3,
                                         uint32_t b0, uint32_t b1) {
    asm volatile(
        "mma.sync.aligned.m16n8k16.row.col.f32.bf16.bf16.f32 "
        "{%0,%1,%2,%3}, {%4,%5,%6,%7}, {%8,%9}, {%0,%1,%2,%3};"
        : "+f"(d[0]), "+f"(d[1]), "+f"(d[2]), "+f"(d[3])
        : "r"(a0), "r"(a1), "r"(a2), "r"(a3), "r"(b0), "r"(b1));
}
__device__ __forceinline__ void cpa16(uint32_t dst, const void* src) {
    asm volatile("cp.async.cg.shared.global [%0], [%1], 16;" :: "r"(dst),
                 "l"(src));
}
__device__ __forceinline__ void cpa_commit() {
    asm volatile("cp.async.commit_group;" ::: "memory");
}
__device__ __forceinline__ void cpa_wait0() {
    asm volatile("cp.async.wait_group 0;" ::: "memory");
}

// ------------------------- K0: token LUT -------------------------
__global__ void k_tok(const int* __restrict__ token_ids) {
    int g = blockIdx.x, l = threadIdx.x;
    int b = g / cT, t = g % cT;
    g_tok[g * cL + l] = token_ids[(t * cL + l) * cB + b];
}

__global__ void k_zero() {
    int idx = blockIdx.x * 256 + threadIdx.x;
    ((float*)g_h)[idx] = 0.0f;
}

// ------------------------- split-precision conversion -------------------------
__global__ void __launch_bounds__(256) k_splitA(const float* __restrict__ emb) {
    size_t idx = ((size_t)blockIdx.x * 256 + threadIdx.x) * 8;
    int row = (int)(idx >> 8);
    float v[8];
    if (row < cV) {
        float4 a = *(const float4*)(emb + idx);
        float4 b = *(const float4*)(emb + idx + 4);
        v[0] = a.x; v[1] = a.y; v[2] = a.z; v[3] = a.w;
        v[4] = b.x; v[5] = b.y; v[6] = b.z; v[7] = b.w;
    } else {
        #pragma unroll
        for (int i = 0; i < 8; i++) v[i] = 0.0f;
    }
    __nv_bfloat16 hi[8], lo[8];
    #pragma unroll
    for (int i = 0; i < 8; i++) {
        hi[i] = __float2bfloat16_rn(v[i]);
        lo[i] = __float2bfloat16_rn(v[i] - __bfloat162float(hi[i]));
    }
    *(uint4*)(g_Ahi + idx) = *(uint4*)hi;
    *(uint4*)(g_Alo + idx) = *(uint4*)lo;
}

// W -> W^T hi/lo bf16 (B operand is [n][k], K-contiguous)
__global__ void __launch_bounds__(256) k_splitB(const float* __restrict__ Wl,
                                                const float* __restrict__ Wr) {
    int z = blockIdx.y, n = blockIdx.x, k = threadIdx.x;
    const float* W = z ? Wr : Wl;
    float x = W[(size_t)k * cD + n];
    __nv_bfloat16 hi = __float2bfloat16_rn(x);
    __nv_bfloat16 lo = __float2bfloat16_rn(x - __bfloat162float(hi));
    g_Bhi[z][n * cD + k] = hi;
    g_Blo[z][n * cD + k] = lo;
}

// ------------------------- K1: mma.sync bf16 split GEMM (A-resident) ------
constexpr int KHS = 264;  // halves per smem row (528 B, pad 8)
constexpr int SM2_AH = 0;
constexpr int SM2_AL = 128 * KHS;
constexpr int SM2_BH = 2 * 128 * KHS;
constexpr int SM2_BL = 2 * 128 * KHS + 64 * KHS;
constexpr int SMEM2 = (2 * 128 * KHS + 2 * 64 * KHS) * 2;  // 202752 B

__global__ void __launch_bounds__(256, 1)
k_gemm2(const float* __restrict__ bl, const float* __restrict__ br) {
    extern __shared__ __nv_bfloat16 sm2[];
    const uint32_t sb = smem_u32(sm2);
    const int tid = threadIdx.x, wid = tid >> 5, lane = tid & 31;
    const int m0 = blockIdx.x * 128;

    #pragma unroll
    for (int i = 0; i < 16; i++) {
        int idx = tid + i * 256;
        int r = idx >> 5, c = idx & 31;
        size_t gs = (size_t)(m0 + r) * cD + c * 8;
        uint32_t d = (uint32_t)((r * KHS + c * 8) * 2);
        cpa16(sb + SM2_AH * 2 + d, g_Ahi + gs);
        cpa16(sb + SM2_AL * 2 + d, g_Alo + gs);
    }
    cpa_commit();

    const int mw = (wid & 1) * 64;
    const int nwp = (wid >> 1) * 16;
    const int aRow = mw + (lane & 15);
    const int aK = (lane >> 4) * 8;
    const int bRow = nwp + (lane & 7);
    const int bK = ((lane >> 3) & 1) * 8;

    #pragma unroll 1
    for (int iter = 0; iter < 8; iter++) {
        const int z = iter >> 2, nc = iter & 3;
        const __nv_bfloat16* __restrict__ gBh = g_Bhi[z];
        const __nv_bfloat16* __restrict__ gBl = g_Blo[z];

        #pragma unroll
        for (int i = 0; i < 8; i++) {
            int idx = tid + i * 256;
            int r = idx >> 5, c = idx & 31;
            size_t gs = (size_t)(nc * 64 + r) * cD + c * 8;
            uint32_t d = (uint32_t)((r * KHS + c * 8) * 2);
            cpa16(sb + SM2_BH * 2 + d, gBh + gs);
            cpa16(sb + SM2_BL * 2 + d, gBl + gs);
        }
        cpa_commit();
        cpa_wait0();
        __syncthreads();

        float acc[4][2][4];
        #pragma unroll
        for (int mi = 0; mi < 4; mi++)
            #pragma unroll
            for (int ni = 0; ni < 2; ni++)
                #pragma unroll
                for (int q = 0; q < 4; q++) acc[mi][ni][q] = 0.0f;

        #pragma unroll 4
        for (int ks = 0; ks < 16; ks++) {
            const int kk = ks * 16;
            uint32_t ah[4][4], al[4][4], bh[2][2], bl2[2][2];
            #pragma unroll
            for (int mi = 0; mi < 4; mi++) {
                uint32_t off =
                    (uint32_t)(((aRow + mi * 16) * KHS + kk + aK) * 2);
                ldm_x4(ah[mi][0], ah[mi][1], ah[mi][2], ah[mi][3],
                       sb + SM2_AH * 2 + off);
                ldm_x4(al[mi][0], al[mi][1], al[mi][2], al[mi][3],
                       sb + SM2_AL * 2 + off);
            }
            #pragma unroll
            for (int ni = 0; ni < 2; ni++) {
                uint32_t off =
                    (uint32_t)(((bRow + ni * 8) * KHS + kk + bK) * 2);
                ldm_x2(bh[ni][0], bh[ni][1], sb + SM2_BH * 2 + off);
                ldm_x2(bl2[ni][0], bl2[ni][1], sb + SM2_BL * 2 + off);
            }
            #pragma unroll
            for (int mi = 0; mi < 4; mi++)
                #pragma unroll
                for (int ni = 0; ni < 2; ni++) {
                    mma16816(acc[mi][ni], ah[mi][0], ah[mi][1], ah[mi][2],
                             ah[mi][3], bh[ni][0], bh[ni][1]);
                    mma16816(acc[mi][ni], ah[mi][0], ah[mi][1], ah[mi][2],
                             ah[mi][3], bl2[ni][0], bl2[ni][1]);
                    mma16816(acc[mi][ni], al[mi][0], al[mi][1], al[mi][2],
                             al[mi][3], bh[ni][0], bh[ni][1]);
                }
        }
        __syncthreads();

        const float* __restrict__ bias = z ? br : bl;
        float* __restrict__ out = z ? g_embR : g_embL;
        const int mbase = m0 + mw + (lane >> 2);
        #pragma unroll
        for (int ni = 0; ni < 2; ni++) {
            int col = nc * 64 + nwp + ni * 8 + (lane & 3) * 2;
            float2 bv = *(const float2*)(bias + col);
            #pragma unroll
            for (int mi = 0; mi < 4; mi++) {
                int mg0 = mbase + mi * 16;
                int mg1 = mg0 + 8;
                if (mg0 < cV) {
                    float2 o = make_float2(acc[mi][ni][0] + bv.x,
                                           acc[mi][ni][1] + bv.y);
                    *(float2*)(out + (size_t)mg0 * cD + col) = o;
                }
                if (mg1 < cV) {
                    float2 o = make_float2(acc[mi][ni][2] + bv.x,
                                           acc[mi][ni][3] + bv.y);
                    *(float2*)(out + (size_t)mg1 * cD + col) = o;
                }
            }
        }
    }
}

// ------------------------- K2: edge pass 1 (w), 2 edges/warp -------------------------
__global__ void __launch_bounds__(256) k_w(const int* __restrict__ eidx,
                                           const float* __restrict__ emb) {
    int wrp = blockIdx.x * 8 + (threadIdx.x >> 5);
    int lane = threadIdx.x & 31;
    int gw0 = wrp * 2;            // edges gw0, gw0+1 (same graph: cE even)
    int g = gw0 / cE;
    int e0 = gw0 % cE;
    const int* __restrict__ srcb = eidx + (size_t)(g * 2) * cE;
    const int* __restrict__ dstb = srcb + cE;
    int s0 = srcb[e0], s1 = srcb[e0 + 1];
    int d0 = dstb[e0], d1 = dstb[e0 + 1];
    int ts0 = g_tok[g * cL + s0], ts1 = g_tok[g * cL + s1];
    int td0 = g_tok[g * cL + d0], td1 = g_tok[g * cL + d1];
    const float4* a0p = (const float4*)(emb + (size_t)ts0 * cD);
    const float4* b0p = (const float4*)(emb + (size_t)td0 * cD);
    const float4* a1p = (const float4*)(emb + (size_t)ts1 * cD);
    const float4* b1p = (const float4*)(emb + (size_t)td1 * cD);
    float ss0 = 0.0f, ss1 = 0.0f;
    #pragma unroll
    for (int i = 0; i < 2; i++) {
        int j = lane + i * 32;
        float4 a0 = a0p[j], b0 = b0p[j], a1 = a1p[j], b1 = b1p[j];
        float x0 = a0.x - b0.x, y0 = a0.y - b0.y, z0 = a0.z - b0.z,
              w0 = a0.w - b0.w;
        float x1 = a1.x - b1.x, y1 = a1.y - b1.y, z1 = a1.z - b1.z,
              w1 = a1.w - b1.w;
        ss0 += x0 * x0 + y0 * y0 + z0 * z0 + w0 * w0;
        ss1 += x1 * x1 + y1 * y1 + z1 * z1 + w1 * w1;
    }
    ss0 = warp_sum(ss0);
    ss1 = warp_sum(ss1);
    if (lane == 0) {
        g_w[gw0] = sqrtf(ss0 + 1e-12f);
        g_w[gw0 + 1] = sqrtf(ss1 + 1e-12f);
    }
}

// ------------------------- K3: beta -------------------------
__global__ void __launch_bounds__(256) k_beta() {
    int g = blockIdx.x, tid = threadIdx.x;
    __shared__ float sm[256];
    float s = 0.0f;
    for (int e = tid; e < cE; e += 256) s += g_w[g * cE + e];
    sm[tid] = s;
    __syncthreads();
    for (int o = 128; o > 0; o >>= 1) {
        if (tid < o) sm[tid] += sm[tid + o];
        __syncthreads();
    }
    if (tid == 0) g_beta[g] = sm[0] / (float)cE;
}

// ------------------------- K4: fused GAT (score+softmax+agg+pool) ----------
__global__ void __launch_bounds__(512) k_gat(const int* __restrict__ eidx,
                                             const float* __restrict__ We,
                                             const float* __restrict__ att,
                                             const float* __restrict__ gbias) {
    const int g = blockIdx.x;
    const int tid = threadIdx.x, lane = tid & 31, wrp = tid >> 5;
    __shared__ int off[cL + 1];
    __shared__ int cnt[cL];
    __shared__ int etok[cE];
    __shared__ float eew[cE];
    __shared__ float spool[cD];

    for (int i = tid; i < cL; i += 512) cnt[i] = 0;
    if (tid < cD) spool[tid] = -1e30f;
    __syncthreads();
    for (int e = tid; e < cE; e += 512) {
        int d = eidx[(size_t)(g * 2 + 1) * cE + e];
        atomicAdd(&cnt[d], 1);
    }
    __syncthreads();
    if (tid == 0) off[0] = 0;
    off[tid + 1] = cnt[tid];
    __syncthreads();
    #pragma unroll
    for (int st = 1; st < cL; st <<= 1) {
        int v = off[tid + 1];
        if (tid >= st) v += off[tid + 1 - st];
        __syncthreads();
        off[tid + 1] = v;
        __syncthreads();
    }
    cnt[tid] = 0;
    __syncthreads();
    {
        float beta = g_beta[g];
        float c = -0.5f / (beta * beta);
        for (int e = tid; e < cE; e += 512) {
            int d = eidx[(size_t)(g * 2 + 1) * cE + e];
            int s = eidx[(size_t)(g * 2) * cE + e];
            int pos = off[d] + atomicAdd(&cnt[d], 1);
            etok[pos] = g_tok[g * cL + s];
            float w = g_w[g * cE + e];
            eew[pos] = expf(w * w * c);
        }
    }
    __syncthreads();

    const int q0 = lane * 4, q1 = 128 + lane * 4;
    const float4 We0 = *(const float4*)(We + q0);
    const float4 We1 = *(const float4*)(We + q1);
    const float4 at0 = *(const float4*)(att + q0);
    const float4 at1 = *(const float4*)(att + q1);
    const float4 gb0 = *(const float4*)(gbias + q0);
    const float4 gb1 = *(const float4*)(gbias + q1);
    float4 pm0 = make_float4(-1e30f, -1e30f, -1e30f, -1e30f);
    float4 pm1 = pm0;

    for (int dst = wrp; dst < cL; dst += 16) {
        int tokd = g_tok[g * cL + dst];
        const float4 xr0 = *(const float4*)(g_embR + (size_t)tokd * cD + q0);
        const float4 xr1 = *(const float4*)(g_embR + (size_t)tokd * cD + q1);
        float m = -1e30f, den = 0.0f;
        float4 a0 = make_float4(0.f, 0.f, 0.f, 0.f), a1 = a0;
        const int pend = off[dst + 1];
        for (int p = off[dst]; p < pend; p++) {
            int tok = etok[p];
            float ew = eew[p];
            const float4 x0 = *(const float4*)(g_embL + (size_t)tok * cD + q0);
            const float4 x1 = *(const float4*)(g_embL + (size_t)tok * cD + q1);
            float vx, par = 0.0f;
            vx = x0.x + xr0.x + ew * We0.x; par += (vx > 0.f ? vx : 0.2f * vx) * at0.x;
            vx = x0.y + xr0.y + ew * We0.y; par += (vx > 0.f ? vx : 0.2f * vx) * at0.y;
            vx = x0.z + xr0.z + ew * We0.z; par += (vx > 0.f ? vx : 0.2f * vx) * at0.z;
            vx = x0.w + xr0.w + ew * We0.w; par += (vx > 0.f ? vx : 0.2f * vx) * at0.w;
            vx = x1.x + xr1.x + ew * We1.x; par += (vx > 0.f ? vx : 0.2f * vx) * at1.x;
            vx = x1.y + xr1.y + ew * We1.y; par += (vx > 0.f ? vx : 0.2f * vx) * at1.y;
            vx = x1.z + xr1.z + ew * We1.z; par += (vx > 0.f ? vx : 0.2f * vx) * at1.z;
            vx = x1.w + xr1.w + ew * We1.w; par += (vx > 0.f ? vx : 0.2f * vx) * at1.w;
            float s = warp_sum(par);
            float mn = fmaxf(m, s);
            float sc = __expf(m - mn);
            float pe = __expf(s - mn);
            den = den * sc + pe;
            a0.x = a0.x * sc + pe * x0.x; a0.y = a0.y * sc + pe * x0.y;
            a0.z = a0.z * sc + pe * x0.z; a0.w = a0.w * sc + pe * x0.w;
            a1.x = a1.x * sc + pe * x1.x; a1.y = a1.y * sc + pe * x1.y;
            a1.z = a1.z * sc + pe * x1.z; a1.w = a1.w * sc + pe * x1.w;
            m = mn;
        }
        float inv = 1.0f / (den + 1e-16f);
        pm0.x = fmaxf(pm0.x, a0.x * inv + gb0.x);
        pm0.y = fmaxf(pm0.y, a0.y * inv + gb0.y);
        pm0.z = fmaxf(pm0.z, a0.z * inv + gb0.z);
        pm0.w = fmaxf(pm0.w, a0.w * inv + gb0.w);
        pm1.x = fmaxf(pm1.x, a1.x * inv + gb1.x);
        pm1.y = fmaxf(pm1.y, a1.y * inv + gb1.y);
        pm1.z = fmaxf(pm1.z, a1.z * inv + gb1.z);
        pm1.w = fmaxf(pm1.w, a1.w * inv + gb1.w);
    }
    atomicMaxF(&spool[q0 + 0], pm0.x);
    atomicMaxF(&spool[q0 + 1], pm0.y);
    atomicMaxF(&spool[q0 + 2], pm0.z);
    atomicMaxF(&spool[q0 + 3], pm0.w);
    atomicMaxF(&spool[q1 + 0], pm1.x);
    atomicMaxF(&spool[q1 + 1], pm1.y);
    atomicMaxF(&spool[q1 + 2], pm1.z);
    atomicMaxF(&spool[q1 + 3], pm1.w);
    __syncthreads();
    if (tid < cD) g_pooled[g * cD + tid] = spool[tid];
}

// ------------------------- K7: GRU input gates (Wih streamed once/block) ---
// grid (16, 2): block = (rgroup of 8 r-values, dir). 8 pooled rows in smem.
__global__ void __launch_bounds__(256) k_gi(const float* __restrict__ Wihf,
                                            const float* __restrict__ bihf,
                                            const float* __restrict__ Wihb,
                                            const float* __restrict__ bihb) {
    const int rg = blockIdx.x, dir = blockIdx.y, tid = threadIdx.x;
    const float* __restrict__ Wih = dir ? Wihb : Wihf;
    const float* __restrict__ bih = dir ? bihb : bihf;
    __shared__ float xs[8][cD];
    for (int i = tid; i < 8 * cD; i += 256) {
        int r = i >> 8, k = i & 255;
        int rr = rg * 8 + r;
        int t = rr / cB, b = rr % cB;
        xs[r][k] = g_pooled[(b * cT + t) * cD + k];
    }
    __syncthreads();
    #pragma unroll
    for (int q = 0; q < 3; q++) {
        int j = q * 256 + tid;
        float acc[8];
        float bj = bih[j];
        #pragma unroll
        for (int r = 0; r < 8; r++) acc[r] = bj;
        const float4* wr = (const float4*)(Wih + (size_t)j * cD);
        #pragma unroll 8
        for (int k4 = 0; k4 < 64; k4++) {
            float4 wv = wr[k4];
            #pragma unroll
            for (int r = 0; r < 8; r++) {
                float4 xx = *(const float4*)&xs[r][k4 * 4];
                acc[r] += wv.x * xx.x + wv.y * xx.y + wv.z * xx.z + wv.w * xx.w;
            }
        }
        #pragma unroll
        for (int r = 0; r < 8; r++)
            g_gi[dir][(size_t)(rg * 8 + r) * 768 + j] = acc[r];
    }
}

// ------------------------- K8: fused GRU (all 8 steps, 1 launch) ----------
// grid (16, 2) = 32 CTAs, all co-resident. Per-dir ticket barrier between
// steps (counter only ever advances by 16 per barrier -> replay-safe).
__global__ void __launch_bounds__(256) k_gru(const float* __restrict__ Whhf,
                                             const float* __restrict__ bhhf,
                                             const float* __restrict__ Whhb,
                                             const float* __restrict__ bhhb) {
    const int dir = blockIdx.y;
    const int tid = threadIdx.x;
    const int b = tid & 15;
    const int jt = tid >> 4;
    const int i = blockIdx.x * 16 + jt;

    const float* __restrict__ Whh = dir ? Whhb : Whhf;
    const float* __restrict__ bhh = dir ? bhhb : bhhf;
    const float bh0 = bhh[i], bh1 = bhh[i + 256], bh2 = bhh[i + 512];
    const float4* w0 = (const float4*)(Whh + (size_t)i * cD);
    const float4* w1 = (const float4*)(Whh + (size_t)(i + 256) * cD);
    const float4* w2 = (const float4*)(Whh + (size_t)(i + 512) * cD);

    __shared__ float h[cB * cH];

    for (int step = 0; step < cT; step++) {
        const int t = (dir == 0) ? step : (cT - 1 - step);
        const int pin = step & 1, pout = (step + 1) & 1;
        for (int idx = tid; idx < cB * cH; idx += 256)
            h[idx] = g_h[dir][pin][idx];
        __syncthreads();

        const float4* hv = (const float4*)(h + b * cH);
        float hr = 0.0f, hz = 0.0f, hn = 0.0f;
        #pragma unroll 4
        for (int k4 = 0; k4 < 64; k4++) {
            float4 hh = hv[k4];
            float4 a = w0[k4], c = w1[k4], d = w2[k4];
            hr += a.x * hh.x + a.y * hh.y + a.z * hh.z + a.w * hh.w;
            hz += c.x * hh.x + c.y * hh.y + c.z * hh.z + c.w * hh.w;
            hn += d.x * hh.x + d.y * hh.y + d.z * hh.z + d.w * hh.w;
        }
        hr += bh0; hz += bh1; hn += bh2;

        const float* gi = &g_gi[dir][(size_t)(t * cB + b) * 768];
        float r = sigmoidf_(gi[i] + hr);
        float z = sigmoidf_(gi[i + 256] + hz);
        float n = tanhf(gi[i + 512] + r * hn);
        float hp = h[b * cH + i];
        float hnew = (1.0f - z) * n + z * hp;

        g_ys[dir][(size_t)(t * cB + b) * cH + i] = hnew;
        g_h[dir][pout][b * cH + i] = hnew;
        __syncthreads();  // h smem reuse safety before next fill

        if (step < cT - 1) {
            if (tid == 0) {
                __threadfence();
                unsigned tk = atomicAdd(&g_grubar[dir], 1u);
                unsigned target = (tk / 16u + 1u) * 16u;
                while (atomicAdd(&g_grubar[dir], 0u) < target) {}
                __threadfence();
            }
            __syncthreads();
        }
    }
}

// ------------------------- K9: finalize output -------------------------
__global__ void __launch_bounds__(256) k_fin(float* __restrict__ out) {
    int idx = blockIdx.x * 256 + threadIdx.x;
    const int n1 = cT * cB * cH;
    const int n2 = n1 + cB * cH;
    if (idx < n1) {
        out[idx] = g_ys[0][idx] + g_ys[1][idx];
    } else if (idx < n2) {
        out[idx] = g_ys[0][(cT - 1) * cB * cH + (idx - n1)];
    } else {
        out[idx] = g_ys[1][idx - n2];
    }
}

// ------------------------- launch -------------------------
extern "C" void kernel_launch(void* const* d_in, const int* in_sizes, int n_in,
                              void* d_out, int out_size) {
    const int*   token_ids = (const int*)d_in[0];
    const int*   edge_index = (const int*)d_in[1];
    const float* emb  = (const float*)d_in[2];
    const float* Wl   = (const float*)d_in[3];
    const float* bl   = (const float*)d_in[4];
    const float* Wr   = (const float*)d_in[5];
    const float* br   = (const float*)d_in[6];
    const float* We   = (const float*)d_in[7];
    const float* att  = (const float*)d_in[8];
    const float* gbias = (const float*)d_in[9];
    const float* Wihf = (const float*)d_in[10];
    const float* Whhf = (const float*)d_in[11];
    const float* bihf = (const float*)d_in[12];
    const float* bhhf = (const float*)d_in[13];
    const float* Wihb = (const float*)d_in[14];
    const float* Whhb = (const float*)d_in[15];
    const float* bihb = (const float*)d_in[16];
    const float* bhhb = (const float*)d_in[17];
    float* out = (float*)d_out;

    static cudaStream_t s2 = nullptr;
    static cudaEvent_t evF = nullptr, evJ = nullptr;
    if (s2 == nullptr) {
        cudaStreamCreateWithFlags(&s2, cudaStreamNonBlocking);
        cudaEventCreateWithFlags(&evF, cudaEventDisableTiming);
        cudaEventCreateWithFlags(&evJ, cudaEventDisableTiming);
    }
    cudaFuncSetAttribute(k_gemm2,
                         cudaFuncAttributeMaxDynamicSharedMemorySize, SMEM2);

    // main stream: tok -> splits -> gemm
    k_tok<<<cG, cL>>>(token_ids);
    cudaEventRecord(evF, 0);
    // side stream: w + beta (depend only on g_tok)
    cudaStreamWaitEvent(s2, evF, 0);
    k_w<<<cG * cE / 16, 256, 0, s2>>>(edge_index, emb);
    k_beta<<<cG, 256, 0, s2>>>();
    cudaEventRecord(evJ, s2);

    k_zero<<<64, 256>>>();
    k_splitA<<<(int)(((size_t)cVp * cD) / (256 * 8)), 256>>>(emb);
    k_splitB<<<dim3(cD, 2), cD>>>(Wl, Wr);
    k_gemm2<<<cVp / 128, 256, SMEM2>>>(bl, br);

    cudaStreamWaitEvent(0, evJ, 0);
    k_gat<<<cG, 512>>>(edge_index, We, att, gbias);
    k_gi<<<dim3(16, 2), 256>>>(Wihf, bihf, Wihb, bihb);
    k_gru<<<dim3(16, 2), 256>>>(Whhf, bhhf, Whhb, bhhb);
    k_fin<<<160, 256>>>(out);
}

// round 8
// speedup vs baseline: 1.8742x; 1.0436x over previous
#include <cuda_runtime.h>
#include <cuda_bf16.h>
#include <cstdint>
#include <math.h>

// Problem constants (fixed by the dataset)
constexpr int cV = 50000;   // vocab
constexpr int cVp = 50048;  // vocab padded to 391*128
constexpr int cD = 256;     // embedding dim
constexpr int cH = 256;     // GRU hidden
constexpr int cB = 16;      // batch
constexpr int cT = 8;       // num_subtrees (time steps)
constexpr int cL = 512;     // subtree_len (nodes per graph)
constexpr int cE = 2048;    // edges per graph
constexpr int cG = cB * cT; // graphs = 128

// ------------------------- device scratch -------------------------
__device__ float g_embL[(size_t)cV * cD];   // emb_table @ Wl + bl
__device__ float g_embR[(size_t)cV * cD];   // emb_table @ Wr + br
__device__ __nv_bfloat16 g_Ahi[(size_t)cVp * cD];
__device__ __nv_bfloat16 g_Alo[(size_t)cVp * cD];
__device__ __nv_bfloat16 g_Bhi[2][cD * cD];  // W^T split hi: [z][n][k]
__device__ __nv_bfloat16 g_Blo[2][cD * cD];
__device__ int   g_tok[cG * cL];
__device__ float g_w[cG * cE];
__device__ float g_beta[cG];
__device__ float g_pooled[cG * cD];
__device__ float g_gi[2][cT * cB * 3 * cH];
__device__ float g_h[2][2][cB * cH];        // [dir][parity][b*H]
__device__ float g_ys[2][cT * cB * cH];
__device__ unsigned g_grubar[2];            // GRU inter-CTA barrier tickets

// ------------------------- small utils -------------------------
__device__ __forceinline__ float warp_sum(float v) {
    #pragma unroll
    for (int o = 16; o > 0; o >>= 1) v += __shfl_xor_sync(0xffffffffu, v, o);
    return v;
}
__device__ __forceinline__ void warp_sum2(float& v0, float& v1) {
    #pragma unroll
    for (int o = 16; o > 0; o >>= 1) {
        v0 += __shfl_xor_sync(0xffffffffu, v0, o);
        v1 += __shfl_xor_sync(0xffffffffu, v1, o);
    }
}
__device__ __forceinline__ void atomicMaxF(float* addr, float val) {
    int* ia = (int*)addr;
    int old = __float_as_int(*addr);
    while (__int_as_float(old) < val) {
        int prev = atomicCAS(ia, old, __float_as_int(val));
        if (prev == old) break;
        old = prev;
    }
}
__device__ __forceinline__ float sigmoidf_(float x) { return 1.0f / (1.0f + expf(-x)); }

// ------------------------- mma.sync helpers -------------------------
__device__ __forceinline__ uint32_t smem_u32(const void* p) {
    uint32_t a;
    asm("{ .reg .u64 t; cvta.to.shared.u64 t, %1; cvt.u32.u64 %0, t; }"
        : "=r"(a) : "l"(p));
    return a;
}
__device__ __forceinline__ void ldm_x4(uint32_t& r0, uint32_t& r1, uint32_t& r2,
                                       uint32_t& r3, uint32_t addr) {
    asm volatile("ldmatrix.sync.aligned.m8n8.x4.shared.b16 {%0,%1,%2,%3}, [%4];"
                 : "=r"(r0), "=r"(r1), "=r"(r2), "=r"(r3) : "r"(addr));
}
__device__ __forceinline__ void ldm_x2(uint32_t& r0, uint32_t& r1, uint32_t addr) {
    asm volatile("ldmatrix.sync.aligned.m8n8.x2.shared.b16 {%0,%1}, [%2];"
                 : "=r"(r0), "=r"(r1) : "r"(addr));
}
__device__ __forceinline__ void mma16816(float* d, uint32_t a0, uint32_t a1,
                                         uint32_t a2, uint32_t a3,
                                         uint32_t b0, uint32_t b1) {
    asm volatile(
        "mma.sync.aligned.m16n8k16.row.col.f32.bf16.bf16.f32 "
        "{%0,%1,%2,%3}, {%4,%5,%6,%7}, {%8,%9}, {%0,%1,%2,%3};"
        : "+f"(d[0]), "+f"(d[1]), "+f"(d[2]), "+f"(d[3])
        : "r"(a0), "r"(a1), "r"(a2), "r"(a3), "r"(b0), "r"(b1));
}
__device__ __forceinline__ void cpa16(uint32_t dst, const void* src) {
    asm volatile("cp.async.cg.shared.global [%0], [%1], 16;" :: "r"(dst),
                 "l"(src));
}
__device__ __forceinline__ void cpa_commit() {
    asm volatile("cp.async.commit_group;" ::: "memory");
}
__device__ __forceinline__ void cpa_wait0() {
    asm volatile("cp.async.wait_group 0;" ::: "memory");
}

// ------------------------- K0: token LUT -------------------------
__global__ void k_tok(const int* __restrict__ token_ids) {
    int g = blockIdx.x, l = threadIdx.x;
    int b = g / cT, t = g % cT;
    g_tok[g * cL + l] = token_ids[(t * cL + l) * cB + b];
}

__global__ void k_zero() {
    int idx = blockIdx.x * 256 + threadIdx.x;
    ((float*)g_h)[idx] = 0.0f;
}

// ------------------------- split-precision conversion -------------------------
__global__ void __launch_bounds__(256) k_splitA(const float* __restrict__ emb) {
    size_t idx = ((size_t)blockIdx.x * 256 + threadIdx.x) * 8;
    int row = (int)(idx >> 8);
    float v[8];
    if (row < cV) {
        float4 a = *(const float4*)(emb + idx);
        float4 b = *(const float4*)(emb + idx + 4);
        v[0] = a.x; v[1] = a.y; v[2] = a.z; v[3] = a.w;
        v[4] = b.x; v[5] = b.y; v[6] = b.z; v[7] = b.w;
    } else {
        #pragma unroll
        for (int i = 0; i < 8; i++) v[i] = 0.0f;
    }
    __nv_bfloat16 hi[8], lo[8];
    #pragma unroll
    for (int i = 0; i < 8; i++) {
        hi[i] = __float2bfloat16_rn(v[i]);
        lo[i] = __float2bfloat16_rn(v[i] - __bfloat162float(hi[i]));
    }
    *(uint4*)(g_Ahi + idx) = *(uint4*)hi;
    *(uint4*)(g_Alo + idx) = *(uint4*)lo;
}

// W -> W^T hi/lo bf16 (B operand is [n][k], K-contiguous)
__global__ void __launch_bounds__(256) k_splitB(const float* __restrict__ Wl,
                                                const float* __restrict__ Wr) {
    int z = blockIdx.y, n = blockIdx.x, k = threadIdx.x;
    const float* W = z ? Wr : Wl;
    float x = W[(size_t)k * cD + n];
    __nv_bfloat16 hi = __float2bfloat16_rn(x);
    __nv_bfloat16 lo = __float2bfloat16_rn(x - __bfloat162float(hi));
    g_Bhi[z][n * cD + k] = hi;
    g_Blo[z][n * cD + k] = lo;
}

// ------------------------- K1: mma.sync bf16 split GEMM (A-resident) ------
constexpr int KHS = 264;  // halves per smem row (528 B, pad 8)
constexpr int SM2_AH = 0;
constexpr int SM2_AL = 128 * KHS;
constexpr int SM2_BH = 2 * 128 * KHS;
constexpr int SM2_BL = 2 * 128 * KHS + 64 * KHS;
constexpr int SMEM2 = (2 * 128 * KHS + 2 * 64 * KHS) * 2;  // 202752 B

__global__ void __launch_bounds__(256, 1)
k_gemm2(const float* __restrict__ bl, const float* __restrict__ br) {
    extern __shared__ __nv_bfloat16 sm2[];
    const uint32_t sb = smem_u32(sm2);
    const int tid = threadIdx.x, wid = tid >> 5, lane = tid & 31;
    const int m0 = blockIdx.x * 128;

    #pragma unroll
    for (int i = 0; i < 16; i++) {
        int idx = tid + i * 256;
        int r = idx >> 5, c = idx & 31;
        size_t gs = (size_t)(m0 + r) * cD + c * 8;
        uint32_t d = (uint32_t)((r * KHS + c * 8) * 2);
        cpa16(sb + SM2_AH * 2 + d, g_Ahi + gs);
        cpa16(sb + SM2_AL * 2 + d, g_Alo + gs);
    }
    cpa_commit();

    const int mw = (wid & 1) * 64;
    const int nwp = (wid >> 1) * 16;
    const int aRow = mw + (lane & 15);
    const int aK = (lane >> 4) * 8;
    const int bRow = nwp + (lane & 7);
    const int bK = ((lane >> 3) & 1) * 8;

    #pragma unroll 1
    for (int iter = 0; iter < 8; iter++) {
        const int z = iter >> 2, nc = iter & 3;
        const __nv_bfloat16* __restrict__ gBh = g_Bhi[z];
        const __nv_bfloat16* __restrict__ gBl = g_Blo[z];

        #pragma unroll
        for (int i = 0; i < 8; i++) {
            int idx = tid + i * 256;
            int r = idx >> 5, c = idx & 31;
            size_t gs = (size_t)(nc * 64 + r) * cD + c * 8;
            uint32_t d = (uint32_t)((r * KHS + c * 8) * 2);
            cpa16(sb + SM2_BH * 2 + d, gBh + gs);
            cpa16(sb + SM2_BL * 2 + d, gBl + gs);
        }
        cpa_commit();
        cpa_wait0();
        __syncthreads();

        float acc[4][2][4];
        #pragma unroll
        for (int mi = 0; mi < 4; mi++)
            #pragma unroll
            for (int ni = 0; ni < 2; ni++)
                #pragma unroll
                for (int q = 0; q < 4; q++) acc[mi][ni][q] = 0.0f;

        #pragma unroll 4
        for (int ks = 0; ks < 16; ks++) {
            const int kk = ks * 16;
            uint32_t ah[4][4], al[4][4], bh[2][2], bl2[2][2];
            #pragma unroll
            for (int mi = 0; mi < 4; mi++) {
                uint32_t off =
                    (uint32_t)(((aRow + mi * 16) * KHS + kk + aK) * 2);
                ldm_x4(ah[mi][0], ah[mi][1], ah[mi][2], ah[mi][3],
                       sb + SM2_AH * 2 + off);
                ldm_x4(al[mi][0], al[mi][1], al[mi][2], al[mi][3],
                       sb + SM2_AL * 2 + off);
            }
            #pragma unroll
            for (int ni = 0; ni < 2; ni++) {
                uint32_t off =
                    (uint32_t)(((bRow + ni * 8) * KHS + kk + bK) * 2);
                ldm_x2(bh[ni][0], bh[ni][1], sb + SM2_BH * 2 + off);
                ldm_x2(bl2[ni][0], bl2[ni][1], sb + SM2_BL * 2 + off);
            }
            #pragma unroll
            for (int mi = 0; mi < 4; mi++)
                #pragma unroll
                for (int ni = 0; ni < 2; ni++) {
                    mma16816(acc[mi][ni], ah[mi][0], ah[mi][1], ah[mi][2],
                             ah[mi][3], bh[ni][0], bh[ni][1]);
                    mma16816(acc[mi][ni], ah[mi][0], ah[mi][1], ah[mi][2],
                             ah[mi][3], bl2[ni][0], bl2[ni][1]);
                    mma16816(acc[mi][ni], al[mi][0], al[mi][1], al[mi][2],
                             al[mi][3], bh[ni][0], bh[ni][1]);
                }
        }
        __syncthreads();

        const float* __restrict__ bias = z ? br : bl;
        float* __restrict__ out = z ? g_embR : g_embL;
        const int mbase = m0 + mw + (lane >> 2);
        #pragma unroll
        for (int ni = 0; ni < 2; ni++) {
            int col = nc * 64 + nwp + ni * 8 + (lane & 3) * 2;
            float2 bv = *(const float2*)(bias + col);
            #pragma unroll
            for (int mi = 0; mi < 4; mi++) {
                int mg0 = mbase + mi * 16;
                int mg1 = mg0 + 8;
                if (mg0 < cV) {
                    float2 o = make_float2(acc[mi][ni][0] + bv.x,
                                           acc[mi][ni][1] + bv.y);
                    *(float2*)(out + (size_t)mg0 * cD + col) = o;
                }
                if (mg1 < cV) {
                    float2 o = make_float2(acc[mi][ni][2] + bv.x,
                                           acc[mi][ni][3] + bv.y);
                    *(float2*)(out + (size_t)mg1 * cD + col) = o;
                }
            }
        }
    }
}

// ------------------------- K2: edge pass 1 (w), 2 edges/warp -------------------------
__global__ void __launch_bounds__(256) k_w(const int* __restrict__ eidx,
                                           const float* __restrict__ emb) {
    int wrp = blockIdx.x * 8 + (threadIdx.x >> 5);
    int lane = threadIdx.x & 31;
    int gw0 = wrp * 2;
    int g = gw0 / cE;
    int e0 = gw0 % cE;
    const int* __restrict__ srcb = eidx + (size_t)(g * 2) * cE;
    const int* __restrict__ dstb = srcb + cE;
    int s0 = srcb[e0], s1 = srcb[e0 + 1];
    int d0 = dstb[e0], d1 = dstb[e0 + 1];
    int ts0 = g_tok[g * cL + s0], ts1 = g_tok[g * cL + s1];
    int td0 = g_tok[g * cL + d0], td1 = g_tok[g * cL + d1];
    const float4* a0p = (const float4*)(emb + (size_t)ts0 * cD);
    const float4* b0p = (const float4*)(emb + (size_t)td0 * cD);
    const float4* a1p = (const float4*)(emb + (size_t)ts1 * cD);
    const float4* b1p = (const float4*)(emb + (size_t)td1 * cD);
    float ss0 = 0.0f, ss1 = 0.0f;
    #pragma unroll
    for (int i = 0; i < 2; i++) {
        int j = lane + i * 32;
        float4 a0 = a0p[j], b0 = b0p[j], a1 = a1p[j], b1 = b1p[j];
        float x0 = a0.x - b0.x, y0 = a0.y - b0.y, z0 = a0.z - b0.z,
              w0 = a0.w - b0.w;
        float x1 = a1.x - b1.x, y1 = a1.y - b1.y, z1 = a1.z - b1.z,
              w1 = a1.w - b1.w;
        ss0 += x0 * x0 + y0 * y0 + z0 * z0 + w0 * w0;
        ss1 += x1 * x1 + y1 * y1 + z1 * z1 + w1 * w1;
    }
    warp_sum2(ss0, ss1);
    if (lane == 0) {
        g_w[gw0] = sqrtf(ss0 + 1e-12f);
        g_w[gw0 + 1] = sqrtf(ss1 + 1e-12f);
    }
}

// ------------------------- K3: beta -------------------------
__global__ void __launch_bounds__(256) k_beta() {
    int g = blockIdx.x, tid = threadIdx.x;
    __shared__ float sm[256];
    float s = 0.0f;
    for (int e = tid; e < cE; e += 256) s += g_w[g * cE + e];
    sm[tid] = s;
    __syncthreads();
    for (int o = 128; o > 0; o >>= 1) {
        if (tid < o) sm[tid] += sm[tid + o];
        __syncthreads();
    }
    if (tid == 0) g_beta[g] = sm[0] / (float)cE;
}

// ------------------------- K4: fused GAT (score+softmax+agg+pool) ----------
__global__ void __launch_bounds__(512) k_gat(const int* __restrict__ eidx,
                                             const float* __restrict__ We,
                                             const float* __restrict__ att,
                                             const float* __restrict__ gbias) {
    const int g = blockIdx.x;
    const int tid = threadIdx.x, lane = tid & 31, wrp = tid >> 5;
    __shared__ int off[cL + 1];
    __shared__ int cnt[cL];
    __shared__ int etok[cE];
    __shared__ float eew[cE];
    __shared__ float spool[cD];

    for (int i = tid; i < cL; i += 512) cnt[i] = 0;
    if (tid < cD) spool[tid] = -1e30f;
    __syncthreads();
    for (int e = tid; e < cE; e += 512) {
        int d = eidx[(size_t)(g * 2 + 1) * cE + e];
        atomicAdd(&cnt[d], 1);
    }
    __syncthreads();
    if (tid == 0) off[0] = 0;
    off[tid + 1] = cnt[tid];
    __syncthreads();
    #pragma unroll
    for (int st = 1; st < cL; st <<= 1) {
        int v = off[tid + 1];
        if (tid >= st) v += off[tid + 1 - st];
        __syncthreads();
        off[tid + 1] = v;
        __syncthreads();
    }
    cnt[tid] = 0;
    __syncthreads();
    {
        float beta = g_beta[g];
        float c = -0.5f / (beta * beta);
        for (int e = tid; e < cE; e += 512) {
            int d = eidx[(size_t)(g * 2 + 1) * cE + e];
            int s = eidx[(size_t)(g * 2) * cE + e];
            int pos = off[d] + atomicAdd(&cnt[d], 1);
            etok[pos] = g_tok[g * cL + s];
            float w = g_w[g * cE + e];
            eew[pos] = __expf(w * w * c);
        }
    }
    __syncthreads();

    const int q0 = lane * 4, q1 = 128 + lane * 4;
    const float4 We0 = *(const float4*)(We + q0);
    const float4 We1 = *(const float4*)(We + q1);
    const float4 at0 = *(const float4*)(att + q0);
    const float4 at1 = *(const float4*)(att + q1);
    const float4 gb0 = *(const float4*)(gbias + q0);
    const float4 gb1 = *(const float4*)(gbias + q1);
    float4 pm0 = make_float4(-1e30f, -1e30f, -1e30f, -1e30f);
    float4 pm1 = pm0;

    for (int dst = wrp; dst < cL; dst += 16) {
        int tokd = g_tok[g * cL + dst];
        const float4 xr0 = *(const float4*)(g_embR + (size_t)tokd * cD + q0);
        const float4 xr1 = *(const float4*)(g_embR + (size_t)tokd * cD + q1);
        float m = -1e30f, den = 0.0f;
        float4 a0 = make_float4(0.f, 0.f, 0.f, 0.f), a1 = a0;
        const int pend = off[dst + 1];
        int p = off[dst];
        // ---- 2 edges per iteration (ILP over gathers + shfl chains) ----
        for (; p + 1 < pend; p += 2) {
            int tA = etok[p], tB = etok[p + 1];
            float ewA = eew[p], ewB = eew[p + 1];
            const float4 xA0 = *(const float4*)(g_embL + (size_t)tA * cD + q0);
            const float4 xA1 = *(const float4*)(g_embL + (size_t)tA * cD + q1);
            const float4 xB0 = *(const float4*)(g_embL + (size_t)tB * cD + q0);
            const float4 xB1 = *(const float4*)(g_embL + (size_t)tB * cD + q1);
            float vx, pa = 0.0f, pb = 0.0f;
            vx = xA0.x + xr0.x + ewA * We0.x; pa += (vx > 0.f ? vx : 0.2f * vx) * at0.x;
            vx = xA0.y + xr0.y + ewA * We0.y; pa += (vx > 0.f ? vx : 0.2f * vx) * at0.y;
            vx = xA0.z + xr0.z + ewA * We0.z; pa += (vx > 0.f ? vx : 0.2f * vx) * at0.z;
            vx = xA0.w + xr0.w + ewA * We0.w; pa += (vx > 0.f ? vx : 0.2f * vx) * at0.w;
            vx = xA1.x + xr1.x + ewA * We1.x; pa += (vx > 0.f ? vx : 0.2f * vx) * at1.x;
            vx = xA1.y + xr1.y + ewA * We1.y; pa += (vx > 0.f ? vx : 0.2f * vx) * at1.y;
            vx = xA1.z + xr1.z + ewA * We1.z; pa += (vx > 0.f ? vx : 0.2f * vx) * at1.z;
            vx = xA1.w + xr1.w + ewA * We1.w; pa += (vx > 0.f ? vx : 0.2f * vx) * at1.w;
            vx = xB0.x + xr0.x + ewB * We0.x; pb += (vx > 0.f ? vx : 0.2f * vx) * at0.x;
            vx = xB0.y + xr0.y + ewB * We0.y; pb += (vx > 0.f ? vx : 0.2f * vx) * at0.y;
            vx = xB0.z + xr0.z + ewB * We0.z; pb += (vx > 0.f ? vx : 0.2f * vx) * at0.z;
            vx = xB0.w + xr0.w + ewB * We0.w; pb += (vx > 0.f ? vx : 0.2f * vx) * at0.w;
            vx = xB1.x + xr1.x + ewB * We1.x; pb += (vx > 0.f ? vx : 0.2f * vx) * at1.x;
            vx = xB1.y + xr1.y + ewB * We1.y; pb += (vx > 0.f ? vx : 0.2f * vx) * at1.y;
            vx = xB1.z + xr1.z + ewB * We1.z; pb += (vx > 0.f ? vx : 0.2f * vx) * at1.z;
            vx = xB1.w + xr1.w + ewB * We1.w; pb += (vx > 0.f ? vx : 0.2f * vx) * at1.w;
            warp_sum2(pa, pb);
            float mn = fmaxf(m, fmaxf(pa, pb));
            float sc = __expf(m - mn);
            float eA = __expf(pa - mn);
            float eB = __expf(pb - mn);
            den = den * sc + eA + eB;
            a0.x = a0.x * sc + eA * xA0.x + eB * xB0.x;
            a0.y = a0.y * sc + eA * xA0.y + eB * xB0.y;
            a0.z = a0.z * sc + eA * xA0.z + eB * xB0.z;
            a0.w = a0.w * sc + eA * xA0.w + eB * xB0.w;
            a1.x = a1.x * sc + eA * xA1.x + eB * xB1.x;
            a1.y = a1.y * sc + eA * xA1.y + eB * xB1.y;
            a1.z = a1.z * sc + eA * xA1.z + eB * xB1.z;
            a1.w = a1.w * sc + eA * xA1.w + eB * xB1.w;
            m = mn;
        }
        // ---- tail edge ----
        if (p < pend) {
            int tok = etok[p];
            float ew = eew[p];
            const float4 x0 = *(const float4*)(g_embL + (size_t)tok * cD + q0);
            const float4 x1 = *(const float4*)(g_embL + (size_t)tok * cD + q1);
            float vx, par = 0.0f;
            vx = x0.x + xr0.x + ew * We0.x; par += (vx > 0.f ? vx : 0.2f * vx) * at0.x;
            vx = x0.y + xr0.y + ew * We0.y; par += (vx > 0.f ? vx : 0.2f * vx) * at0.y;
            vx = x0.z + xr0.z + ew * We0.z; par += (vx > 0.f ? vx : 0.2f * vx) * at0.z;
            vx = x0.w + xr0.w + ew * We0.w; par += (vx > 0.f ? vx : 0.2f * vx) * at0.w;
            vx = x1.x + xr1.x + ew * We1.x; par += (vx > 0.f ? vx : 0.2f * vx) * at1.x;
            vx = x1.y + xr1.y + ew * We1.y; par += (vx > 0.f ? vx : 0.2f * vx) * at1.y;
            vx = x1.z + xr1.z + ew * We1.z; par += (vx > 0.f ? vx : 0.2f * vx) * at1.z;
            vx = x1.w + xr1.w + ew * We1.w; par += (vx > 0.f ? vx : 0.2f * vx) * at1.w;
            float s = warp_sum(par);
            float mn = fmaxf(m, s);
            float sc = __expf(m - mn);
            float pe = __expf(s - mn);
            den = den * sc + pe;
            a0.x = a0.x * sc + pe * x0.x; a0.y = a0.y * sc + pe * x0.y;
            a0.z = a0.z * sc + pe * x0.z; a0.w = a0.w * sc + pe * x0.w;
            a1.x = a1.x * sc + pe * x1.x; a1.y = a1.y * sc + pe * x1.y;
            a1.z = a1.z * sc + pe * x1.z; a1.w = a1.w * sc + pe * x1.w;
        }
        float inv = 1.0f / (den + 1e-16f);
        pm0.x = fmaxf(pm0.x, a0.x * inv + gb0.x);
        pm0.y = fmaxf(pm0.y, a0.y * inv + gb0.y);
        pm0.z = fmaxf(pm0.z, a0.z * inv + gb0.z);
        pm0.w = fmaxf(pm0.w, a0.w * inv + gb0.w);
        pm1.x = fmaxf(pm1.x, a1.x * inv + gb1.x);
        pm1.y = fmaxf(pm1.y, a1.y * inv + gb1.y);
        pm1.z = fmaxf(pm1.z, a1.z * inv + gb1.z);
        pm1.w = fmaxf(pm1.w, a1.w * inv + gb1.w);
    }
    atomicMaxF(&spool[q0 + 0], pm0.x);
    atomicMaxF(&spool[q0 + 1], pm0.y);
    atomicMaxF(&spool[q0 + 2], pm0.z);
    atomicMaxF(&spool[q0 + 3], pm0.w);
    atomicMaxF(&spool[q1 + 0], pm1.x);
    atomicMaxF(&spool[q1 + 1], pm1.y);
    atomicMaxF(&spool[q1 + 2], pm1.z);
    atomicMaxF(&spool[q1 + 3], pm1.w);
    __syncthreads();
    if (tid < cD) g_pooled[g * cD + tid] = spool[tid];
}

// ------------------------- K7: GRU input gates (Wih streamed once/block) ---
__global__ void __launch_bounds__(256) k_gi(const float* __restrict__ Wihf,
                                            const float* __restrict__ bihf,
                                            const float* __restrict__ Wihb,
                                            const float* __restrict__ bihb) {
    const int rg = blockIdx.x, dir = blockIdx.y, tid = threadIdx.x;
    const float* __restrict__ Wih = dir ? Wihb : Wihf;
    const float* __restrict__ bih = dir ? bihb : bihf;
    __shared__ float xs[8][cD];
    for (int i = tid; i < 8 * cD; i += 256) {
        int r = i >> 8, k = i & 255;
        int rr = rg * 8 + r;
        int t = rr / cB, b = rr % cB;
        xs[r][k] = g_pooled[(b * cT + t) * cD + k];
    }
    __syncthreads();
    #pragma unroll
    for (int q = 0; q < 3; q++) {
        int j = q * 256 + tid;
        float acc[8];
        float bj = bih[j];
        #pragma unroll
        for (int r = 0; r < 8; r++) acc[r] = bj;
        const float4* wr = (const float4*)(Wih + (size_t)j * cD);
        #pragma unroll 8
        for (int k4 = 0; k4 < 64; k4++) {
            float4 wv = wr[k4];
            #pragma unroll
            for (int r = 0; r < 8; r++) {
                float4 xx = *(const float4*)&xs[r][k4 * 4];
                acc[r] += wv.x * xx.x + wv.y * xx.y + wv.z * xx.z + wv.w * xx.w;
            }
        }
        #pragma unroll
        for (int r = 0; r < 8; r++)
            g_gi[dir][(size_t)(rg * 8 + r) * 768 + j] = acc[r];
    }
}

// ------------------------- K8: fused GRU (all 8 steps, 1 launch) ----------
__global__ void __launch_bounds__(256) k_gru(const float* __restrict__ Whhf,
                                             const float* __restrict__ bhhf,
                                             const float* __restrict__ Whhb,
                                             const float* __restrict__ bhhb) {
    const int dir = blockIdx.y;
    const int tid = threadIdx.x;
    const int b = tid & 15;
    const int jt = tid >> 4;
    const int i = blockIdx.x * 16 + jt;

    const float* __restrict__ Whh = dir ? Whhb : Whhf;
    const float* __restrict__ bhh = dir ? bhhb : bhhf;
    const float bh0 = bhh[i], bh1 = bhh[i + 256], bh2 = bhh[i + 512];
    const float4* w0 = (const float4*)(Whh + (size_t)i * cD);
    const float4* w1 = (const float4*)(Whh + (size_t)(i + 256) * cD);
    const float4* w2 = (const float4*)(Whh + (size_t)(i + 512) * cD);

    __shared__ float h[cB * cH];

    for (int step = 0; step < cT; step++) {
        const int t = (dir == 0) ? step : (cT - 1 - step);
        const int pin = step & 1, pout = (step + 1) & 1;
        for (int idx = tid; idx < cB * cH; idx += 256)
            h[idx] = g_h[dir][pin][idx];
        __syncthreads();

        const float4* hv = (const float4*)(h + b * cH);
        float hr = 0.0f, hz = 0.0f, hn = 0.0f;
        #pragma unroll 4
        for (int k4 = 0; k4 < 64; k4++) {
            float4 hh = hv[k4];
            float4 a = w0[k4], c = w1[k4], d = w2[k4];
            hr += a.x * hh.x + a.y * hh.y + a.z * hh.z + a.w * hh.w;
            hz += c.x * hh.x + c.y * hh.y + c.z * hh.z + c.w * hh.w;
            hn += d.x * hh.x + d.y * hh.y + d.z * hh.z + d.w * hh.w;
        }
        hr += bh0; hz += bh1; hn += bh2;

        const float* gi = &g_gi[dir][(size_t)(t * cB + b) * 768];
        float r = sigmoidf_(gi[i] + hr);
        float z = sigmoidf_(gi[i + 256] + hz);
        float n = tanhf(gi[i + 512] + r * hn);
        float hp = h[b * cH + i];
        float hnew = (1.0f - z) * n + z * hp;

        g_ys[dir][(size_t)(t * cB + b) * cH + i] = hnew;
        g_h[dir][pout][b * cH + i] = hnew;
        __syncthreads();

        if (step < cT - 1) {
            if (tid == 0) {
                __threadfence();
                unsigned tk = atomicAdd(&g_grubar[dir], 1u);
                unsigned target = (tk / 16u + 1u) * 16u;
                while (atomicAdd(&g_grubar[dir], 0u) < target) {}
                __threadfence();
            }
            __syncthreads();
        }
    }
}

// ------------------------- K9: finalize output -------------------------
__global__ void __launch_bounds__(256) k_fin(float* __restrict__ out) {
    int idx = blockIdx.x * 256 + threadIdx.x;
    const int n1 = cT * cB * cH;
    const int n2 = n1 + cB * cH;
    if (idx < n1) {
        out[idx] = g_ys[0][idx] + g_ys[1][idx];
    } else if (idx < n2) {
        out[idx] = g_ys[0][(cT - 1) * cB * cH + (idx - n1)];
    } else {
        out[idx] = g_ys[1][idx - n2];
    }
}

// ------------------------- launch -------------------------
extern "C" void kernel_launch(void* const* d_in, const int* in_sizes, int n_in,
                              void* d_out, int out_size) {
    const int*   token_ids = (const int*)d_in[0];
    const int*   edge_index = (const int*)d_in[1];
    const float* emb  = (const float*)d_in[2];
    const float* Wl   = (const float*)d_in[3];
    const float* bl   = (const float*)d_in[4];
    const float* Wr   = (const float*)d_in[5];
    const float* br   = (const float*)d_in[6];
    const float* We   = (const float*)d_in[7];
    const float* att  = (const float*)d_in[8];
    const float* gbias = (const float*)d_in[9];
    const float* Wihf = (const float*)d_in[10];
    const float* Whhf = (const float*)d_in[11];
    const float* bihf = (const float*)d_in[12];
    const float* bhhf = (const float*)d_in[13];
    const float* Wihb = (const float*)d_in[14];
    const float* Whhb = (const float*)d_in[15];
    const float* bihb = (const float*)d_in[16];
    const float* bhhb = (const float*)d_in[17];
    float* out = (float*)d_out;

    static cudaStream_t s2 = nullptr;
    static cudaEvent_t evF = nullptr, evJ = nullptr;
    if (s2 == nullptr) {
        cudaStreamCreateWithFlags(&s2, cudaStreamNonBlocking);
        cudaEventCreateWithFlags(&evF, cudaEventDisableTiming);
        cudaEventCreateWithFlags(&evJ, cudaEventDisableTiming);
    }
    cudaFuncSetAttribute(k_gemm2,
                         cudaFuncAttributeMaxDynamicSharedMemorySize, SMEM2);

    // Submission order puts k_gemm2 at launch #4 (ncu captures the 4th
    // launch); execution order is unchanged (dependency-driven).
    k_tok<<<cG, cL>>>(token_ids);                                     // #1
    cudaEventRecord(evF, 0);
    k_splitA<<<(int)(((size_t)cVp * cD) / (256 * 8)), 256>>>(emb);    // #2
    k_splitB<<<dim3(cD, 2), cD>>>(Wl, Wr);                            // #3
    k_gemm2<<<cVp / 128, 256, SMEM2>>>(bl, br);                       // #4
    // side stream: w + beta overlap the split/gemm chain
    cudaStreamWaitEvent(s2, evF, 0);
    k_w<<<cG * cE / 16, 256, 0, s2>>>(edge_index, emb);               // #5
    k_beta<<<cG, 256, 0, s2>>>();                                     // #6
    cudaEventRecord(evJ, s2);

    k_zero<<<64, 256>>>();                                            // #7
    cudaStreamWaitEvent(0, evJ, 0);
    k_gat<<<cG, 512>>>(edge_index, We, att, gbias);                   // #8
    k_gi<<<dim3(16, 2), 256>>>(Wihf, bihf, Wihb, bihb);               // #9
    k_gru<<<dim3(16, 2), 256>>>(Whhf, bhhf, Whhb, bhhb);              // #10
    k_fin<<<160, 256>>>(out);                                         // #11
}

// round 10
// speedup vs baseline: 1.9920x; 1.0629x over previous
#include <cuda_runtime.h>
#include <cuda_bf16.h>
#include <cstdint>
#include <math.h>

// Problem constants (fixed by the dataset)
constexpr int cV = 50000;   // vocab
constexpr int cVp = 50048;  // vocab padded to 391*128
constexpr int cD = 256;     // embedding dim
constexpr int cH = 256;     // GRU hidden
constexpr int cB = 16;      // batch
constexpr int cT = 8;       // num_subtrees (time steps)
constexpr int cL = 512;     // subtree_len (nodes per graph)
constexpr int cE = 2048;    // edges per graph
constexpr int cG = cB * cT; // graphs = 128

// ------------------------- device scratch -------------------------
__device__ float g_embL[(size_t)cV * cD];   // emb_table @ Wl + bl
__device__ float g_embR[(size_t)cV * cD];   // emb_table @ Wr + br
__device__ __nv_bfloat16 g_Ahi[(size_t)cVp * cD];
__device__ __nv_bfloat16 g_Alo[(size_t)cVp * cD];
__device__ __nv_bfloat16 g_Bhi[2][cD * cD];  // W^T split hi: [z][n][k]
__device__ __nv_bfloat16 g_Blo[2][cD * cD];
__device__ int   g_tok[cG * cL];
__device__ float g_w[cG * cE];
__device__ float g_beta[cG];
__device__ float g_pooled[cG * cD];
__device__ float g_gi[2][cT * cB * 3 * cH];
__device__ float g_h[2][2][cB * cH];        // [dir][parity][b*H]
__device__ float g_ys[2][cT * cB * cH];
__device__ unsigned g_grubar[2];            // GRU inter-CTA barrier tickets

// ------------------------- small utils -------------------------
__device__ __forceinline__ float warp_sum(float v) {
    #pragma unroll
    for (int o = 16; o > 0; o >>= 1) v += __shfl_xor_sync(0xffffffffu, v, o);
    return v;
}
__device__ __forceinline__ void warp_sum2(float& v0, float& v1) {
    #pragma unroll
    for (int o = 16; o > 0; o >>= 1) {
        v0 += __shfl_xor_sync(0xffffffffu, v0, o);
        v1 += __shfl_xor_sync(0xffffffffu, v1, o);
    }
}
__device__ __forceinline__ void atomicMaxF(float* addr, float val) {
    int* ia = (int*)addr;
    int old = __float_as_int(*addr);
    while (__int_as_float(old) < val) {
        int prev = atomicCAS(ia, old, __float_as_int(val));
        if (prev == old) break;
        old = prev;
    }
}
__device__ __forceinline__ float sigmoidf_(float x) { return 1.0f / (1.0f + expf(-x)); }

// ------------------------- mma.sync helpers -------------------------
__device__ __forceinline__ uint32_t smem_u32(const void* p) {
    uint32_t a;
    asm("{ .reg .u64 t; cvta.to.shared.u64 t, %1; cvt.u32.u64 %0, t; }"
        : "=r"(a) : "l"(p));
    return a;
}
__device__ __forceinline__ void ldm_x4(uint32_t& r0, uint32_t& r1, uint32_t& r2,
                                       uint32_t& r3, uint32_t addr) {
    asm volatile("ldmatrix.sync.aligned.m8n8.x4.shared.b16 {%0,%1,%2,%3}, [%4];"
                 : "=r"(r0), "=r"(r1), "=r"(r2), "=r"(r3) : "r"(addr));
}
__device__ __forceinline__ void mma16816(float* d, uint32_t a0, uint32_t a1,
                                         uint32_t a2, uint32_t a3,
                                         uint32_t b0, uint32_t b1) {
    asm volatile(
        "mma.sync.aligned.m16n8k16.row.col.f32.bf16.bf16.f32 "
        "{%0,%1,%2,%3}, {%4,%5,%6,%7}, {%8,%9}, {%0,%1,%2,%3};"
        : "+f"(d[0]), "+f"(d[1]), "+f"(d[2]), "+f"(d[3])
        : "r"(a0), "r"(a1), "r"(a2), "r"(a3), "r"(b0), "r"(b1));
}
__device__ __forceinline__ void cpa16(uint32_t dst, const void* src) {
    asm volatile("cp.async.cg.shared.global [%0], [%1], 16;" :: "r"(dst),
                 "l"(src));
}
__device__ __forceinline__ void cpa_commit() {
    asm volatile("cp.async.commit_group;" ::: "memory");
}
__device__ __forceinline__ void cpa_wait0() {
    asm volatile("cp.async.wait_group 0;" ::: "memory");
}

// ------------------------- K0: token LUT -------------------------
__global__ void k_tok(const int* __restrict__ token_ids) {
    int g = blockIdx.x, l = threadIdx.x;
    int b = g / cT, t = g % cT;
    g_tok[g * cL + l] = token_ids[(t * cL + l) * cB + b];
}

__global__ void k_zero() {
    int idx = blockIdx.x * 256 + threadIdx.x;
    ((float*)g_h)[idx] = 0.0f;
}

// ------------------------- split-precision conversion -------------------------
__global__ void __launch_bounds__(256) k_splitA(const float* __restrict__ emb) {
    size_t idx = ((size_t)blockIdx.x * 256 + threadIdx.x) * 8;
    int row = (int)(idx >> 8);
    float v[8];
    if (row < cV) {
        float4 a = *(const float4*)(emb + idx);
        float4 b = *(const float4*)(emb + idx + 4);
        v[0] = a.x; v[1] = a.y; v[2] = a.z; v[3] = a.w;
        v[4] = b.x; v[5] = b.y; v[6] = b.z; v[7] = b.w;
    } else {
        #pragma unroll
        for (int i = 0; i < 8; i++) v[i] = 0.0f;
    }
    __nv_bfloat16 hi[8], lo[8];
    #pragma unroll
    for (int i = 0; i < 8; i++) {
        hi[i] = __float2bfloat16_rn(v[i]);
        lo[i] = __float2bfloat16_rn(v[i] - __bfloat162float(hi[i]));
    }
    *(uint4*)(g_Ahi + idx) = *(uint4*)hi;
    *(uint4*)(g_Alo + idx) = *(uint4*)lo;
}

// W -> W^T hi/lo bf16 (B operand is [n][k], K-contiguous)
__global__ void __launch_bounds__(256) k_splitB(const float* __restrict__ Wl,
                                                const float* __restrict__ Wr) {
    int z = blockIdx.y, n = blockIdx.x, k = threadIdx.x;
    const float* W = z ? Wr : Wl;
    float x = W[(size_t)k * cD + n];
    __nv_bfloat16 hi = __float2bfloat16_rn(x);
    __nv_bfloat16 lo = __float2bfloat16_rn(x - __bfloat162float(hi));
    g_Bhi[z][n * cD + k] = hi;
    g_Blo[z][n * cD + k] = lo;
}

// ------------------------- K1: mma.sync bf16 split GEMM v3 ----------------
// Tile 128x128, grid (4 combos = nhalf+2*z, 391 m-tiles). 72KB smem,
// launch_bounds(256,2) -> 2 CTAs/SM. K chunks of 64 staged via cp.async.
// Warp grid 2m x 4n, warp tile 64x32. B frags via ldmatrix.x4 (2 n-blocks).
constexpr int SST = 72;                       // halves per smem row (144B)
constexpr int TILE3 = 128 * SST;              // halves per tile
constexpr int SMEM3 = 4 * TILE3 * 2;          // 73728 B

__global__ void __launch_bounds__(256, 2)
k_gemm3(const float* __restrict__ bl, const float* __restrict__ br) {
    extern __shared__ __nv_bfloat16 sm3[];
    const uint32_t sb = smem_u32(sm3);
    const uint32_t uAh = sb;
    const uint32_t uAl = sb + TILE3 * 2;
    const uint32_t uBh = sb + 2 * TILE3 * 2;
    const uint32_t uBl = sb + 3 * TILE3 * 2;

    const int tid = threadIdx.x, wid = tid >> 5, lane = tid & 31;
    const int m0 = blockIdx.y * 128;
    const int nhalf = blockIdx.x & 1, z = blockIdx.x >> 1;
    const int n0 = nhalf * 128;
    const __nv_bfloat16* __restrict__ gBh = g_Bhi[z];
    const __nv_bfloat16* __restrict__ gBl = g_Blo[z];

    const int mw = (wid & 1) * 64;   // warp m offset
    const int nw = (wid >> 1) * 32;  // warp n offset
    const int aRow = mw + (lane & 15);
    const int aK = (lane >> 4) * 8;
    // B ldmatrix.x4 lane address: two 8-row n-blocks x two k-halves
    const int bN = ((lane >> 4) & 1) * 8 + (lane & 7);
    const int bK = ((lane >> 3) & 1) * 8;

    float acc[4][4][4];
    #pragma unroll
    for (int mi = 0; mi < 4; mi++)
        #pragma unroll
        for (int ni = 0; ni < 4; ni++)
            #pragma unroll
            for (int q = 0; q < 4; q++) acc[mi][ni][q] = 0.0f;

    for (int kb = 0; kb < 256; kb += 64) {
        // stage A (128 rows x 64 halves) hi+lo
        #pragma unroll
        for (int i = 0; i < 4; i++) {
            int idx = tid + i * 256;
            int r = idx >> 3, s = idx & 7;
            size_t gs = (size_t)(m0 + r) * cD + kb + s * 8;
            uint32_t d = (uint32_t)((r * SST + s * 8) * 2);
            cpa16(uAh + d, g_Ahi + gs);
            cpa16(uAl + d, g_Alo + gs);
        }
        // stage B (128 n-rows x 64 halves) hi+lo
        #pragma unroll
        for (int i = 0; i < 4; i++) {
            int idx = tid + i * 256;
            int r = idx >> 3, s = idx & 7;
            size_t gs = (size_t)(n0 + r) * cD + kb + s * 8;
            uint32_t d = (uint32_t)((r * SST + s * 8) * 2);
            cpa16(uBh + d, gBh + gs);
            cpa16(uBl + d, gBl + gs);
        }
        cpa_commit();
        cpa_wait0();
        __syncthreads();

        #pragma unroll
        for (int ks = 0; ks < 4; ks++) {
            const int kk = ks * 16;
            uint32_t ah[4][4], al[4][4], bh[4][2], bl2[4][2];
            #pragma unroll
            for (int mi = 0; mi < 4; mi++) {
                uint32_t off =
                    (uint32_t)(((aRow + mi * 16) * SST + kk + aK) * 2);
                ldm_x4(ah[mi][0], ah[mi][1], ah[mi][2], ah[mi][3], uAh + off);
                ldm_x4(al[mi][0], al[mi][1], al[mi][2], al[mi][3], uAl + off);
            }
            #pragma unroll
            for (int nj = 0; nj < 2; nj++) {
                uint32_t off =
                    (uint32_t)(((nw + nj * 16 + bN) * SST + kk + bK) * 2);
                ldm_x4(bh[2 * nj][0], bh[2 * nj][1], bh[2 * nj + 1][0],
                       bh[2 * nj + 1][1], uBh + off);
                ldm_x4(bl2[2 * nj][0], bl2[2 * nj][1], bl2[2 * nj + 1][0],
                       bl2[2 * nj + 1][1], uBl + off);
            }
            #pragma unroll
            for (int mi = 0; mi < 4; mi++)
                #pragma unroll
                for (int ni = 0; ni < 4; ni++) {
                    mma16816(acc[mi][ni], ah[mi][0], ah[mi][1], ah[mi][2],
                             ah[mi][3], bh[ni][0], bh[ni][1]);
                    mma16816(acc[mi][ni], ah[mi][0], ah[mi][1], ah[mi][2],
                             ah[mi][3], bl2[ni][0], bl2[ni][1]);
                    mma16816(acc[mi][ni], al[mi][0], al[mi][1], al[mi][2],
                             al[mi][3], bh[ni][0], bh[ni][1]);
                }
        }
        __syncthreads();
    }

    const float* __restrict__ bias = z ? br : bl;
    float* __restrict__ out = z ? g_embR : g_embL;
    const int mbase = m0 + mw + (lane >> 2);
    #pragma unroll
    for (int ni = 0; ni < 4; ni++) {
        int col = n0 + nw + ni * 8 + (lane & 3) * 2;
        float2 bv = *(const float2*)(bias + col);
        #pragma unroll
        for (int mi = 0; mi < 4; mi++) {
            int mg0 = mbase + mi * 16;
            int mg1 = mg0 + 8;
            if (mg0 < cV) {
                float2 o = make_float2(acc[mi][ni][0] + bv.x,
                                       acc[mi][ni][1] + bv.y);
                *(float2*)(out + (size_t)mg0 * cD + col) = o;
            }
            if (mg1 < cV) {
                float2 o = make_float2(acc[mi][ni][2] + bv.x,
                                       acc[mi][ni][3] + bv.y);
                *(float2*)(out + (size_t)mg1 * cD + col) = o;
            }
        }
    }
}

// ------------------------- K2: edge pass 1 (w), 2 edges/warp -------------------------
__global__ void __launch_bounds__(256) k_w(const int* __restrict__ eidx,
                                           const float* __restrict__ emb) {
    int wrp = blockIdx.x * 8 + (threadIdx.x >> 5);
    int lane = threadIdx.x & 31;
    int gw0 = wrp * 2;
    int g = gw0 / cE;
    int e0 = gw0 % cE;
    const int* __restrict__ srcb = eidx + (size_t)(g * 2) * cE;
    const int* __restrict__ dstb = srcb + cE;
    int s0 = srcb[e0], s1 = srcb[e0 + 1];
    int d0 = dstb[e0], d1 = dstb[e0 + 1];
    int ts0 = g_tok[g * cL + s0], ts1 = g_tok[g * cL + s1];
    int td0 = g_tok[g * cL + d0], td1 = g_tok[g * cL + d1];
    const float4* a0p = (const float4*)(emb + (size_t)ts0 * cD);
    const float4* b0p = (const float4*)(emb + (size_t)td0 * cD);
    const float4* a1p = (const float4*)(emb + (size_t)ts1 * cD);
    const float4* b1p = (const float4*)(emb + (size_t)td1 * cD);
    float ss0 = 0.0f, ss1 = 0.0f;
    #pragma unroll
    for (int i = 0; i < 2; i++) {
        int j = lane + i * 32;
        float4 a0 = a0p[j], b0 = b0p[j], a1 = a1p[j], b1 = b1p[j];
        float x0 = a0.x - b0.x, y0 = a0.y - b0.y, z0 = a0.z - b0.z,
              w0 = a0.w - b0.w;
        float x1 = a1.x - b1.x, y1 = a1.y - b1.y, z1 = a1.z - b1.z,
              w1 = a1.w - b1.w;
        ss0 += x0 * x0 + y0 * y0 + z0 * z0 + w0 * w0;
        ss1 += x1 * x1 + y1 * y1 + z1 * z1 + w1 * w1;
    }
    warp_sum2(ss0, ss1);
    if (lane == 0) {
        g_w[gw0] = sqrtf(ss0 + 1e-12f);
        g_w[gw0 + 1] = sqrtf(ss1 + 1e-12f);
    }
}

// ------------------------- K3: beta -------------------------
__global__ void __launch_bounds__(256) k_beta() {
    int g = blockIdx.x, tid = threadIdx.x;
    __shared__ float sm[256];
    float s = 0.0f;
    for (int e = tid; e < cE; e += 256) s += g_w[g * cE + e];
    sm[tid] = s;
    __syncthreads();
    for (int o = 128; o > 0; o >>= 1) {
        if (tid < o) sm[tid] += sm[tid + o];
        __syncthreads();
    }
    if (tid == 0) g_beta[g] = sm[0] / (float)cE;
}

// ------------------------- K4: fused GAT (score+softmax+agg+pool) ----------
__global__ void __launch_bounds__(512) k_gat(const int* __restrict__ eidx,
                                             const float* __restrict__ We,
                                             const float* __restrict__ att,
                                             const float* __restrict__ gbias) {
    const int g = blockIdx.x;
    const int tid = threadIdx.x, lane = tid & 31, wrp = tid >> 5;
    __shared__ int off[cL + 1];
    __shared__ int cnt[cL];
    __shared__ int etok[cE];
    __shared__ float eew[cE];
    __shared__ float spool[cD];

    for (int i = tid; i < cL; i += 512) cnt[i] = 0;
    if (tid < cD) spool[tid] = -1e30f;
    __syncthreads();
    for (int e = tid; e < cE; e += 512) {
        int d = eidx[(size_t)(g * 2 + 1) * cE + e];
        atomicAdd(&cnt[d], 1);
    }
    __syncthreads();
    if (tid == 0) off[0] = 0;
    off[tid + 1] = cnt[tid];
    __syncthreads();
    #pragma unroll
    for (int st = 1; st < cL; st <<= 1) {
        int v = off[tid + 1];
        if (tid >= st) v += off[tid + 1 - st];
        __syncthreads();
        off[tid + 1] = v;
        __syncthreads();
    }
    cnt[tid] = 0;
    __syncthreads();
    {
        float beta = g_beta[g];
        float c = -0.5f / (beta * beta);
        for (int e = tid; e < cE; e += 512) {
            int d = eidx[(size_t)(g * 2 + 1) * cE + e];
            int s = eidx[(size_t)(g * 2) * cE + e];
            int pos = off[d] + atomicAdd(&cnt[d], 1);
            etok[pos] = g_tok[g * cL + s];
            float w = g_w[g * cE + e];
            eew[pos] = __expf(w * w * c);
        }
    }
    __syncthreads();

    const int q0 = lane * 4, q1 = 128 + lane * 4;
    const float4 We0 = *(const float4*)(We + q0);
    const float4 We1 = *(const float4*)(We + q1);
    const float4 at0 = *(const float4*)(att + q0);
    const float4 at1 = *(const float4*)(att + q1);
    const float4 gb0 = *(const float4*)(gbias + q0);
    const float4 gb1 = *(const float4*)(gbias + q1);
    float4 pm0 = make_float4(-1e30f, -1e30f, -1e30f, -1e30f);
    float4 pm1 = pm0;

    for (int dst = wrp; dst < cL; dst += 16) {
        int tokd = g_tok[g * cL + dst];
        const float4 xr0 = *(const float4*)(g_embR + (size_t)tokd * cD + q0);
        const float4 xr1 = *(const float4*)(g_embR + (size_t)tokd * cD + q1);
        float m = -1e30f, den = 0.0f;
        float4 a0 = make_float4(0.f, 0.f, 0.f, 0.f), a1 = a0;
        const int pend = off[dst + 1];
        int p = off[dst];
        for (; p + 1 < pend; p += 2) {
            int tA = etok[p], tB = etok[p + 1];
            float ewA = eew[p], ewB = eew[p + 1];
            const float4 xA0 = *(const float4*)(g_embL + (size_t)tA * cD + q0);
            const float4 xA1 = *(const float4*)(g_embL + (size_t)tA * cD + q1);
            const float4 xB0 = *(const float4*)(g_embL + (size_t)tB * cD + q0);
            const float4 xB1 = *(const float4*)(g_embL + (size_t)tB * cD + q1);
            float vx, pa = 0.0f, pb = 0.0f;
            vx = xA0.x + xr0.x + ewA * We0.x; pa += (vx > 0.f ? vx : 0.2f * vx) * at0.x;
            vx = xA0.y + xr0.y + ewA * We0.y; pa += (vx > 0.f ? vx : 0.2f * vx) * at0.y;
            vx = xA0.z + xr0.z + ewA * We0.z; pa += (vx > 0.f ? vx : 0.2f * vx) * at0.z;
            vx = xA0.w + xr0.w + ewA * We0.w; pa += (vx > 0.f ? vx : 0.2f * vx) * at0.w;
            vx = xA1.x + xr1.x + ewA * We1.x; pa += (vx > 0.f ? vx : 0.2f * vx) * at1.x;
            vx = xA1.y + xr1.y + ewA * We1.y; pa += (vx > 0.f ? vx : 0.2f * vx) * at1.y;
            vx = xA1.z + xr1.z + ewA * We1.z; pa += (vx > 0.f ? vx : 0.2f * vx) * at1.z;
            vx = xA1.w + xr1.w + ewA * We1.w; pa += (vx > 0.f ? vx : 0.2f * vx) * at1.w;
            vx = xB0.x + xr0.x + ewB * We0.x; pb += (vx > 0.f ? vx : 0.2f * vx) * at0.x;
            vx = xB0.y + xr0.y + ewB * We0.y; pb += (vx > 0.f ? vx : 0.2f * vx) * at0.y;
            vx = xB0.z + xr0.z + ewB * We0.z; pb += (vx > 0.f ? vx : 0.2f * vx) * at0.z;
            vx = xB0.w + xr0.w + ewB * We0.w; pb += (vx > 0.f ? vx : 0.2f * vx) * at0.w;
            vx = xB1.x + xr1.x + ewB * We1.x; pb += (vx > 0.f ? vx : 0.2f * vx) * at1.x;
            vx = xB1.y + xr1.y + ewB * We1.y; pb += (vx > 0.f ? vx : 0.2f * vx) * at1.y;
            vx = xB1.z + xr1.z + ewB * We1.z; pb += (vx > 0.f ? vx : 0.2f * vx) * at1.z;
            vx = xB1.w + xr1.w + ewB * We1.w; pb += (vx > 0.f ? vx : 0.2f * vx) * at1.w;
            warp_sum2(pa, pb);
            float mn = fmaxf(m, fmaxf(pa, pb));
            float sc = __expf(m - mn);
            float eA = __expf(pa - mn);
            float eB = __expf(pb - mn);
            den = den * sc + eA + eB;
            a0.x = a0.x * sc + eA * xA0.x + eB * xB0.x;
            a0.y = a0.y * sc + eA * xA0.y + eB * xB0.y;
            a0.z = a0.z * sc + eA * xA0.z + eB * xB0.z;
            a0.w = a0.w * sc + eA * xA0.w + eB * xB0.w;
            a1.x = a1.x * sc + eA * xA1.x + eB * xB1.x;
            a1.y = a1.y * sc + eA * xA1.y + eB * xB1.y;
            a1.z = a1.z * sc + eA * xA1.z + eB * xB1.z;
            a1.w = a1.w * sc + eA * xA1.w + eB * xB1.w;
            m = mn;
        }
        if (p < pend) {
            int tok = etok[p];
            float ew = eew[p];
            const float4 x0 = *(const float4*)(g_embL + (size_t)tok * cD + q0);
            const float4 x1 = *(const float4*)(g_embL + (size_t)tok * cD + q1);
            float vx, par = 0.0f;
            vx = x0.x + xr0.x + ew * We0.x; par += (vx > 0.f ? vx : 0.2f * vx) * at0.x;
            vx = x0.y + xr0.y + ew * We0.y; par += (vx > 0.f ? vx : 0.2f * vx) * at0.y;
            vx = x0.z + xr0.z + ew * We0.z; par += (vx > 0.f ? vx : 0.2f * vx) * at0.z;
            vx = x0.w + xr0.w + ew * We0.w; par += (vx > 0.f ? vx : 0.2f * vx) * at0.w;
            vx = x1.x + xr1.x + ew * We1.x; par += (vx > 0.f ? vx : 0.2f * vx) * at1.x;
            vx = x1.y + xr1.y + ew * We1.y; par += (vx > 0.f ? vx : 0.2f * vx) * at1.y;
            vx = x1.z + xr1.z + ew * We1.z; par += (vx > 0.f ? vx : 0.2f * vx) * at1.z;
            vx = x1.w + xr1.w + ew * We1.w; par += (vx > 0.f ? vx : 0.2f * vx) * at1.w;
            float s = warp_sum(par);
            float mn = fmaxf(m, s);
            float sc = __expf(m - mn);
            float pe = __expf(s - mn);
            den = den * sc + pe;
            a0.x = a0.x * sc + pe * x0.x; a0.y = a0.y * sc + pe * x0.y;
            a0.z = a0.z * sc + pe * x0.z; a0.w = a0.w * sc + pe * x0.w;
            a1.x = a1.x * sc + pe * x1.x; a1.y = a1.y * sc + pe * x1.y;
            a1.z = a1.z * sc + pe * x1.z; a1.w = a1.w * sc + pe * x1.w;
        }
        float inv = 1.0f / (den + 1e-16f);
        pm0.x = fmaxf(pm0.x, a0.x * inv + gb0.x);
        pm0.y = fmaxf(pm0.y, a0.y * inv + gb0.y);
        pm0.z = fmaxf(pm0.z, a0.z * inv + gb0.z);
        pm0.w = fmaxf(pm0.w, a0.w * inv + gb0.w);
        pm1.x = fmaxf(pm1.x, a1.x * inv + gb1.x);
        pm1.y = fmaxf(pm1.y, a1.y * inv + gb1.y);
        pm1.z = fmaxf(pm1.z, a1.z * inv + gb1.z);
        pm1.w = fmaxf(pm1.w, a1.w * inv + gb1.w);
    }
    atomicMaxF(&spool[q0 + 0], pm0.x);
    atomicMaxF(&spool[q0 + 1], pm0.y);
    atomicMaxF(&spool[q0 + 2], pm0.z);
    atomicMaxF(&spool[q0 + 3], pm0.w);
    atomicMaxF(&spool[q1 + 0], pm1.x);
    atomicMaxF(&spool[q1 + 1], pm1.y);
    atomicMaxF(&spool[q1 + 2], pm1.z);
    atomicMaxF(&spool[q1 + 3], pm1.w);
    __syncthreads();
    if (tid < cD) g_pooled[g * cD + tid] = spool[tid];
}

// ------------------------- K7: GRU input gates (Wih streamed once/block) ---
__global__ void __launch_bounds__(256) k_gi(const float* __restrict__ Wihf,
                                            const float* __restrict__ bihf,
                                            const float* __restrict__ Wihb,
                                            const float* __restrict__ bihb) {
    const int rg = blockIdx.x, dir = blockIdx.y, tid = threadIdx.x;
    const float* __restrict__ Wih = dir ? Wihb : Wihf;
    const float* __restrict__ bih = dir ? bihb : bihf;
    __shared__ float xs[8][cD];
    for (int i = tid; i < 8 * cD; i += 256) {
        int r = i >> 8, k = i & 255;
        int rr = rg * 8 + r;
        int t = rr / cB, b = rr % cB;
        xs[r][k] = g_pooled[(b * cT + t) * cD + k];
    }
    __syncthreads();
    #pragma unroll
    for (int q = 0; q < 3; q++) {
        int j = q * 256 + tid;
        float acc[8];
        float bj = bih[j];
        #pragma unroll
        for (int r = 0; r < 8; r++) acc[r] = bj;
        const float4* wr = (const float4*)(Wih + (size_t)j * cD);
        #pragma unroll 8
        for (int k4 = 0; k4 < 64; k4++) {
            float4 wv = wr[k4];
            #pragma unroll
            for (int r = 0; r < 8; r++) {
                float4 xx = *(const float4*)&xs[r][k4 * 4];
                acc[r] += wv.x * xx.x + wv.y * xx.y + wv.z * xx.z + wv.w * xx.w;
            }
        }
        #pragma unroll
        for (int r = 0; r < 8; r++)
            g_gi[dir][(size_t)(rg * 8 + r) * 768 + j] = acc[r];
    }
}

// ------------------------- K8: fused GRU (all 8 steps, 1 launch) ----------
__global__ void __launch_bounds__(256) k_gru(const float* __restrict__ Whhf,
                                             const float* __restrict__ bhhf,
                                             const float* __restrict__ Whhb,
                                             const float* __restrict__ bhhb) {
    const int dir = blockIdx.y;
    const int tid = threadIdx.x;
    const int b = tid & 15;
    const int jt = tid >> 4;
    const int i = blockIdx.x * 16 + jt;

    const float* __restrict__ Whh = dir ? Whhb : Whhf;
    const float* __restrict__ bhh = dir ? bhhb : bhhf;
    const float bh0 = bhh[i], bh1 = bhh[i + 256], bh2 = bhh[i + 512];
    const float4* w0 = (const float4*)(Whh + (size_t)i * cD);
    const float4* w1 = (const float4*)(Whh + (size_t)(i + 256) * cD);
    const float4* w2 = (const float4*)(Whh + (size_t)(i + 512) * cD);

    __shared__ float h[cB * cH];

    for (int step = 0; step < cT; step++) {
        const int t = (dir == 0) ? step : (cT - 1 - step);
        const int pin = step & 1, pout = (step + 1) & 1;
        for (int idx = tid; idx < cB * cH; idx += 256)
            h[idx] = g_h[dir][pin][idx];
        __syncthreads();

        const float4* hv = (const float4*)(h + b * cH);
        float hr = 0.0f, hz = 0.0f, hn = 0.0f;
        #pragma unroll 4
        for (int k4 = 0; k4 < 64; k4++) {
            float4 hh = hv[k4];
            float4 a = w0[k4], c = w1[k4], d = w2[k4];
            hr += a.x * hh.x + a.y * hh.y + a.z * hh.z + a.w * hh.w;
            hz += c.x * hh.x + c.y * hh.y + c.z * hh.z + c.w * hh.w;
            hn += d.x * hh.x + d.y * hh.y + d.z * hh.z + d.w * hh.w;
        }
        hr += bh0; hz += bh1; hn += bh2;

        const float* gi = &g_gi[dir][(size_t)(t * cB + b) * 768];
        float r = sigmoidf_(gi[i] + hr);
        float z = sigmoidf_(gi[i + 256] + hz);
        float n = tanhf(gi[i + 512] + r * hn);
        float hp = h[b * cH + i];
        float hnew = (1.0f - z) * n + z * hp;

        g_ys[dir][(size_t)(t * cB + b) * cH + i] = hnew;
        g_h[dir][pout][b * cH + i] = hnew;
        __syncthreads();

        if (step < cT - 1) {
            if (tid == 0) {
                __threadfence();
                unsigned tk = atomicAdd(&g_grubar[dir], 1u);
                unsigned target = (tk / 16u + 1u) * 16u;
                while (atomicAdd(&g_grubar[dir], 0u) < target) {}
                __threadfence();
            }
            __syncthreads();
        }
    }
}

// ------------------------- K9: finalize output -------------------------
__global__ void __launch_bounds__(256) k_fin(float* __restrict__ out) {
    int idx = blockIdx.x * 256 + threadIdx.x;
    const int n1 = cT * cB * cH;
    const int n2 = n1 + cB * cH;
    if (idx < n1) {
        out[idx] = g_ys[0][idx] + g_ys[1][idx];
    } else if (idx < n2) {
        out[idx] = g_ys[0][(cT - 1) * cB * cH + (idx - n1)];
    } else {
        out[idx] = g_ys[1][idx - n2];
    }
}

// ------------------------- launch -------------------------
extern "C" void kernel_launch(void* const* d_in, const int* in_sizes, int n_in,
                              void* d_out, int out_size) {
    const int*   token_ids = (const int*)d_in[0];
    const int*   edge_index = (const int*)d_in[1];
    const float* emb  = (const float*)d_in[2];
    const float* Wl   = (const float*)d_in[3];
    const float* bl   = (const float*)d_in[4];
    const float* Wr   = (const float*)d_in[5];
    const float* br   = (const float*)d_in[6];
    const float* We   = (const float*)d_in[7];
    const float* att  = (const float*)d_in[8];
    const float* gbias = (const float*)d_in[9];
    const float* Wihf = (const float*)d_in[10];
    const float* Whhf = (const float*)d_in[11];
    const float* bihf = (const float*)d_in[12];
    const float* bhhf = (const float*)d_in[13];
    const float* Wihb = (const float*)d_in[14];
    const float* Whhb = (const float*)d_in[15];
    const float* bihb = (const float*)d_in[16];
    const float* bhhb = (const float*)d_in[17];
    float* out = (float*)d_out;

    static cudaStream_t s2 = nullptr;
    static cudaEvent_t evF = nullptr, evJ = nullptr;
    if (s2 == nullptr) {
        cudaStreamCreateWithFlags(&s2, cudaStreamNonBlocking);
        cudaEventCreateWithFlags(&evF, cudaEventDisableTiming);
        cudaEventCreateWithFlags(&evJ, cudaEventDisableTiming);
    }
    cudaFuncSetAttribute(k_gemm3,
                         cudaFuncAttributeMaxDynamicSharedMemorySize, SMEM3);

    // k_gemm3 stays launch #4 for ncu visibility.
    k_tok<<<cG, cL>>>(token_ids);                                     // #1
    cudaEventRecord(evF, 0);
    k_splitA<<<(int)(((size_t)cVp * cD) / (256 * 8)), 256>>>(emb);    // #2
    k_splitB<<<dim3(cD, 2), cD>>>(Wl, Wr);                            // #3
    k_gemm3<<<dim3(4, cVp / 128), 256, SMEM3>>>(bl, br);              // #4
    // side stream: w + beta overlap the split/gemm chain
    cudaStreamWaitEvent(s2, evF, 0);
    k_w<<<cG * cE / 16, 256, 0, s2>>>(edge_index, emb);               // #5
    k_beta<<<cG, 256, 0, s2>>>();                                     // #6
    cudaEventRecord(evJ, s2);

    k_zero<<<64, 256>>>();                                            // #7
    cudaStreamWaitEvent(0, evJ, 0);
    k_gat<<<cG, 512>>>(edge_index, We, att, gbias);                   // #8
    k_gi<<<dim3(16, 2), 256>>>(Wihf, bihf, Wihb, bihb);               // #9
    k_gru<<<dim3(16, 2), 256>>>(Whhf, bhhf, Whhb, bhhb);              // #10
    k_fin<<<160, 256>>>(out);                                         // #11
}